// round 1
// baseline (speedup 1.0000x reference)
#include <cuda_runtime.h>
#include <math.h>
#include <float.h>

#define SLEN 2048
#define DM   2048
#define NH   16
#define NKV  4
#define DH   128

// Scratch (allocation-free rule: __device__ globals)
__device__ float g_Q[SLEN * DM];        // [p][h*128+k]  16 MB
__device__ float g_K[SLEN * NKV * DH];  // [p][kvh*128+k] 4 MB
__device__ float g_V[SLEN * NKV * DH];  // 4 MB
__device__ float g_Z[SLEN * DM];        // attention out, [p][h*128+d] 16 MB

// ---------------------------------------------------------------------------
// Generic fp32 SGEMM: C = A * B + bias.  Tiles: BM=BN=128, BK=8, 256 thr, 8x8.
// blockIdx.z selects a weight/output slice (per-head projections).
// All dims are multiples of 128 / K multiple of 8 -> no bounds checks.
// ---------------------------------------------------------------------------
__global__ __launch_bounds__(256) void sgemm_kernel(
    const float* __restrict__ A, int lda,
    const float* __restrict__ B, int ldb, long bStride,
    float* __restrict__ C, int ldc, long cStride,
    const float* __restrict__ bias, long biasStride,
    int K)
{
    __shared__ float As[8][128];   // [k][m]
    __shared__ float Bs[8][128];   // [k][n]

    const int tid = threadIdx.x;
    const int ty  = tid >> 4;      // 0..15  -> m
    const int tx  = tid & 15;      // 0..15  -> n
    const int mblk = blockIdx.x * 128;
    const int nblk = blockIdx.y * 128;
    const int z    = blockIdx.z;

    const float* Bz   = B + (long)z * bStride;
    float*       Cz   = C + (long)z * cStride;
    const float* bz   = bias + (long)z * biasStride;

    const int arow  = mblk + (tid >> 1);
    const int acol0 = (tid & 1) * 4;
    const int brow0 = tid >> 5;                 // 0..7
    const int bcol  = nblk + (tid & 31) * 4;

    float acc[8][8];
#pragma unroll
    for (int i = 0; i < 8; i++)
#pragma unroll
        for (int j = 0; j < 8; j++) acc[i][j] = 0.f;

    for (int k0 = 0; k0 < K; k0 += 8) {
        float4 a4 = *(const float4*)(A  + (long)arow * lda + k0 + acol0);
        float4 b4 = *(const float4*)(Bz + (long)(k0 + brow0) * ldb + bcol);
        __syncthreads();
        As[acol0 + 0][tid >> 1] = a4.x;
        As[acol0 + 1][tid >> 1] = a4.y;
        As[acol0 + 2][tid >> 1] = a4.z;
        As[acol0 + 3][tid >> 1] = a4.w;
        *(float4*)(&Bs[brow0][(tid & 31) * 4]) = b4;
        __syncthreads();
#pragma unroll
        for (int k = 0; k < 8; k++) {
            float4 a0 = *(const float4*)(&As[k][ty * 8]);
            float4 a1 = *(const float4*)(&As[k][ty * 8 + 4]);
            float4 b0 = *(const float4*)(&Bs[k][tx * 8]);
            float4 b1 = *(const float4*)(&Bs[k][tx * 8 + 4]);
            float av[8] = {a0.x, a0.y, a0.z, a0.w, a1.x, a1.y, a1.z, a1.w};
            float bv[8] = {b0.x, b0.y, b0.z, b0.w, b1.x, b1.y, b1.z, b1.w};
#pragma unroll
            for (int i = 0; i < 8; i++)
#pragma unroll
                for (int j = 0; j < 8; j++)
                    acc[i][j] = fmaf(av[i], bv[j], acc[i][j]);
        }
    }

#pragma unroll
    for (int i = 0; i < 8; i++) {
        const int row = mblk + ty * 8 + i;
#pragma unroll
        for (int j = 0; j < 8; j += 4) {
            const int col = nblk + tx * 8 + j;
            float4 r;
            r.x = acc[i][j + 0] + bz[col + 0];
            r.y = acc[i][j + 1] + bz[col + 1];
            r.z = acc[i][j + 2] + bz[col + 2];
            r.w = acc[i][j + 3] + bz[col + 3];
            *(float4*)(Cz + (long)row * ldc + col) = r;
        }
    }
}

// ---------------------------------------------------------------------------
// Rotary (rotate-half, full 128-dim).  One block per (pos, head), 128 threads.
// Double-precision trig: immune to fast-math arg-reduction error at |x|~2047.
// ---------------------------------------------------------------------------
__global__ __launch_bounds__(128) void rotary_kernel(float* __restrict__ X, int nheads)
{
    const int p = blockIdx.x;
    const int h = blockIdx.y;
    const int i = threadIdx.x;
    float* row = X + ((long)p * nheads + h) * DH;

    const int ip = (i < 64) ? i : (i - 64);
    // freq = 10000^(ip/64); angle = p / freq
    const double freq = exp(9.210340371976184 * ((double)ip / 64.0));
    const double ang  = (double)p / freq;
    const float s = (float)sin(ang);
    const float c = (float)cos(ang);

    const float xi = row[i];
    const float xp = (i < 64) ? row[i + 64] : row[i - 64];
    __syncthreads();
    row[i] = (i < 64) ? (xi * c - xp * s) : (xi * c + xp * s);
}

// ---------------------------------------------------------------------------
// Causal flash attention.  BQ=BK=64, D=128, 256 threads.
// Thread layout: ty=tid/16 owns rows ty*4..+3 in both the S-stage (4x4 over
// tx*4 cols) and the PV-stage (8 dims at tx*8) so m/l stats stay in-register.
// Shuffle row-reductions stay inside 16-lane halves (xor<=8).
// ---------------------------------------------------------------------------
__global__ __launch_bounds__(256) void attn_kernel()
{
    extern __shared__ float sm[];
    float* sQ  = sm;           // [64][128]
    float* sKT = sm + 8192;    // [128][64]  (k-major for vector B reads)
    float* sV  = sm + 16384;   // [64][128]
    float* sP  = sm + 24576;   // [64][64]

    const int qb  = blockIdx.x;        // 0..31
    const int h   = blockIdx.y;        // 0..15
    const int kvh = h >> 2;
    const int tid = threadIdx.x;
    const int ty  = tid >> 4;
    const int tx  = tid & 15;
    const int q0  = qb * 64;
    const float scale = 0.08838834764831845f;  // 1/sqrt(128)

    // Q tile (coalesced float4)
#pragma unroll
    for (int t = 0; t < 8; t++) {
        int idx = t * 256 + tid;
        int r = idx >> 5, c4 = idx & 31;
        *(float4*)(sQ + r * DH + c4 * 4) =
            *(const float4*)(g_Q + (long)(q0 + r) * DM + h * DH + c4 * 4);
    }

    float o[4][8];
    float m_i[4], l_i[4];
#pragma unroll
    for (int i = 0; i < 4; i++) {
        m_i[i] = -INFINITY; l_i[i] = 0.f;
#pragma unroll
        for (int d = 0; d < 8; d++) o[i][d] = 0.f;
    }

    for (int kb = 0; kb <= qb; kb++) {
        const int k0 = kb * 64;
        __syncthreads();   // previous tile/sP fully consumed
        // K (transposed into sKT, conflict-free stores) + V tiles
#pragma unroll
        for (int t = 0; t < 8; t++) {
            int idx = t * 256 + tid;
            {
                int j = idx & 63, c4 = idx >> 6;
                float4 kv = *(const float4*)(g_K + (long)(k0 + j) * (NKV * DH) + kvh * DH + c4 * 4);
                sKT[(c4 * 4 + 0) * 64 + j] = kv.x;
                sKT[(c4 * 4 + 1) * 64 + j] = kv.y;
                sKT[(c4 * 4 + 2) * 64 + j] = kv.z;
                sKT[(c4 * 4 + 3) * 64 + j] = kv.w;
            }
            {
                int r = idx >> 5, c4 = idx & 31;
                *(float4*)(sV + r * DH + c4 * 4) =
                    *(const float4*)(g_V + (long)(k0 + r) * (NKV * DH) + kvh * DH + c4 * 4);
            }
        }
        __syncthreads();

        // S = Q K^T (4x4 per thread)
        float cs[4][4] = {};
#pragma unroll 4
        for (int k = 0; k < DH; k++) {
            float4 b = *(const float4*)(sKT + k * 64 + tx * 4);
#pragma unroll
            for (int ii = 0; ii < 4; ii++) {
                float a = sQ[(ty * 4 + ii) * DH + k];
                cs[ii][0] = fmaf(a, b.x, cs[ii][0]);
                cs[ii][1] = fmaf(a, b.y, cs[ii][1]);
                cs[ii][2] = fmaf(a, b.z, cs[ii][2]);
                cs[ii][3] = fmaf(a, b.w, cs[ii][3]);
            }
        }

        const bool diag = (kb == qb);
#pragma unroll
        for (int ii = 0; ii < 4; ii++) {
            const int qi = q0 + ty * 4 + ii;
#pragma unroll
            for (int jj = 0; jj < 4; jj++) {
                float sv = cs[ii][jj] * scale;
                if (diag && (k0 + tx * 4 + jj) > qi) sv = -INFINITY;
                cs[ii][jj] = sv;
            }
            float mx = fmaxf(fmaxf(cs[ii][0], cs[ii][1]), fmaxf(cs[ii][2], cs[ii][3]));
            mx = fmaxf(mx, __shfl_xor_sync(0xffffffffu, mx, 8));
            mx = fmaxf(mx, __shfl_xor_sync(0xffffffffu, mx, 4));
            mx = fmaxf(mx, __shfl_xor_sync(0xffffffffu, mx, 2));
            mx = fmaxf(mx, __shfl_xor_sync(0xffffffffu, mx, 1));
            const float mnew = fmaxf(m_i[ii], mx);
            const float corr = __expf(m_i[ii] - mnew);  // 0 when m_i=-inf
            m_i[ii] = mnew;
            float rs = 0.f;
#pragma unroll
            for (int jj = 0; jj < 4; jj++) {
                float p = __expf(cs[ii][jj] - mnew);
                cs[ii][jj] = p;
                rs += p;
            }
            rs += __shfl_xor_sync(0xffffffffu, rs, 8);
            rs += __shfl_xor_sync(0xffffffffu, rs, 4);
            rs += __shfl_xor_sync(0xffffffffu, rs, 2);
            rs += __shfl_xor_sync(0xffffffffu, rs, 1);
            l_i[ii] = l_i[ii] * corr + rs;
#pragma unroll
            for (int d = 0; d < 8; d++) o[ii][d] *= corr;
            *(float4*)(sP + (ty * 4 + ii) * 64 + tx * 4) =
                make_float4(cs[ii][0], cs[ii][1], cs[ii][2], cs[ii][3]);
        }
        __syncthreads();

        // O += P V  (4 rows x 8 dims per thread)
#pragma unroll 2
        for (int j = 0; j < 64; j++) {
            float4 v0 = *(const float4*)(sV + j * DH + tx * 8);
            float4 v1 = *(const float4*)(sV + j * DH + tx * 8 + 4);
#pragma unroll
            for (int ii = 0; ii < 4; ii++) {
                float p = sP[(ty * 4 + ii) * 64 + j];
                o[ii][0] = fmaf(p, v0.x, o[ii][0]);
                o[ii][1] = fmaf(p, v0.y, o[ii][1]);
                o[ii][2] = fmaf(p, v0.z, o[ii][2]);
                o[ii][3] = fmaf(p, v0.w, o[ii][3]);
                o[ii][4] = fmaf(p, v1.x, o[ii][4]);
                o[ii][5] = fmaf(p, v1.y, o[ii][5]);
                o[ii][6] = fmaf(p, v1.z, o[ii][6]);
                o[ii][7] = fmaf(p, v1.w, o[ii][7]);
            }
        }
    }

#pragma unroll
    for (int ii = 0; ii < 4; ii++) {
        const float inv = 1.f / l_i[ii];
        const long base = (long)(q0 + ty * 4 + ii) * DM + h * DH + tx * 8;
        *(float4*)(g_Z + base)     = make_float4(o[ii][0] * inv, o[ii][1] * inv,
                                                 o[ii][2] * inv, o[ii][3] * inv);
        *(float4*)(g_Z + base + 4) = make_float4(o[ii][4] * inv, o[ii][5] * inv,
                                                 o[ii][6] * inv, o[ii][7] * inv);
    }
}

// ---------------------------------------------------------------------------
static float* symAddr(const void* sym)
{
    void* p = nullptr;
    cudaGetSymbolAddress(&p, sym);
    return (float*)p;
}

extern "C" void kernel_launch(void* const* d_in, const int* in_sizes, int n_in,
                              void* d_out, int out_size)
{
    const float* Xq = (const float*)d_in[0];
    const float* Xk = (const float*)d_in[1];
    const float* Xv = (const float*)d_in[2];
    const float* WQ = (const float*)d_in[3];
    const float* bQ = (const float*)d_in[4];
    const float* WK = (const float*)d_in[5];
    const float* bK = (const float*)d_in[6];
    const float* WV = (const float*)d_in[7];
    const float* bV = (const float*)d_in[8];
    const float* WO = (const float*)d_in[9];
    const float* bO = (const float*)d_in[10];
    float* out = (float*)d_out;

    float* Qb = symAddr(g_Q);
    float* Kb = symAddr(g_K);
    float* Vb = symAddr(g_V);
    float* Zb = symAddr(g_Z);

    // Projections: per-head [2048,2048]x[2048,128] GEMMs (blockIdx.z = head)
    sgemm_kernel<<<dim3(16, 1, NH), 256>>>(
        Xq, DM, WQ, DH, (long)DM * DH, Qb, DM, DH, bQ, DH, DM);
    sgemm_kernel<<<dim3(16, 1, NKV), 256>>>(
        Xk, DM, WK, DH, (long)DM * DH, Kb, NKV * DH, DH, bK, DH, DM);
    sgemm_kernel<<<dim3(16, 1, NKV), 256>>>(
        Xv, DM, WV, DH, (long)DM * DH, Vb, NKV * DH, DH, bV, DH, DM);

    // Rotary on Q and K
    rotary_kernel<<<dim3(SLEN, NH), 128>>>(Qb, NH);
    rotary_kernel<<<dim3(SLEN, NKV), 128>>>(Kb, NKV);

    // Causal flash attention
    const int attn_smem = (64 * 128 + 128 * 64 + 64 * 128 + 64 * 64) * (int)sizeof(float);
    cudaFuncSetAttribute(attn_kernel, cudaFuncAttributeMaxDynamicSharedMemorySize, attn_smem);
    attn_kernel<<<dim3(SLEN / 64, NH), 256, attn_smem>>>();

    // Output projection: [2048,2048] x [2048,2048] + b_O
    sgemm_kernel<<<dim3(16, 16, 1), 256>>>(
        Zb, DM, WO, DM, 0, out, DM, 0, bO, 0, DM);
}

// round 5
// speedup vs baseline: 1.5181x; 1.5181x over previous
#include <cuda_runtime.h>
#include <cuda_bf16.h>
#include <cstdint>
#include <math.h>
#include <float.h>

#define SLEN 2048
#define DM   2048
#define NH   16
#define NKV  4
#define DH   128

// ---------------- scratch (__device__ globals; no allocs allowed) ----------
__device__ float g_Q[SLEN * DM];
__device__ float g_K[SLEN * NKV * DH];
__device__ float g_V[SLEN * NKV * DH];
__device__ float g_Z[SLEN * DM];

__device__ __nv_bfloat16 g_xqh[SLEN * DM], g_xql[SLEN * DM];
__device__ __nv_bfloat16 g_xkh[SLEN * DM], g_xkl[SLEN * DM];
__device__ __nv_bfloat16 g_xvh[SLEN * DM], g_xvl[SLEN * DM];
__device__ __nv_bfloat16 g_zh [SLEN * DM], g_zl [SLEN * DM];
__device__ __nv_bfloat16 g_wqh[NH  * DH * DM], g_wql[NH  * DH * DM];
__device__ __nv_bfloat16 g_wkh[NKV * DH * DM], g_wkl[NKV * DH * DM];
__device__ __nv_bfloat16 g_wvh[NKV * DH * DM], g_wvl[NKV * DH * DM];
__device__ __nv_bfloat16 g_woh[DM * DM],       g_wol[DM * DM];

// ---------------- helpers (sm_80-level features only) ----------------------
static __device__ __forceinline__ uint32_t s2u(const void* p) {
    uint32_t a;
    asm("{ .reg .u64 t; cvta.to.shared.u64 t, %1; cvt.u32.u64 %0, t; }"
        : "=r"(a) : "l"(p));
    return a;
}
static __device__ __forceinline__ void cp16(uint32_t dst, const void* src) {
    asm volatile("cp.async.cg.shared.global [%0], [%1], 16;"
                 :: "r"(dst), "l"(src) : "memory");
}
static __device__ __forceinline__ void cp_commit() {
    asm volatile("cp.async.commit_group;" ::: "memory");
}
template <int N>
static __device__ __forceinline__ void cp_wait() {
    asm volatile("cp.async.wait_group %0;" :: "n"(N) : "memory");
}
static __device__ __forceinline__ void ldm_x4(uint32_t& r0, uint32_t& r1,
                                              uint32_t& r2, uint32_t& r3, uint32_t a) {
    asm volatile("ldmatrix.sync.aligned.m8n8.x4.shared.b16 {%0,%1,%2,%3}, [%4];"
                 : "=r"(r0), "=r"(r1), "=r"(r2), "=r"(r3) : "r"(a));
}
static __device__ __forceinline__ void ldm_x2(uint32_t& r0, uint32_t& r1, uint32_t a) {
    asm volatile("ldmatrix.sync.aligned.m8n8.x2.shared.b16 {%0,%1}, [%2];"
                 : "=r"(r0), "=r"(r1) : "r"(a));
}
static __device__ __forceinline__ void mma16816(float* d, const uint32_t* a,
                                                const uint32_t* b) {
    asm volatile(
        "mma.sync.aligned.m16n8k16.row.col.f32.bf16.bf16.f32 "
        "{%0,%1,%2,%3}, {%4,%5,%6,%7}, {%8,%9}, {%0,%1,%2,%3};"
        : "+f"(d[0]), "+f"(d[1]), "+f"(d[2]), "+f"(d[3])
        : "r"(a[0]), "r"(a[1]), "r"(a[2]), "r"(a[3]), "r"(b[0]), "r"(b[1]));
}

// ---------------------------------------------------------------------------
// fp32 -> (bf16 hi, bf16 lo) elementwise split.
// ---------------------------------------------------------------------------
__global__ __launch_bounds__(256) void split_kernel(
    const float* __restrict__ x, __nv_bfloat16* __restrict__ h,
    __nv_bfloat16* __restrict__ l, int n)
{
    int i = (blockIdx.x * 256 + threadIdx.x) * 4;
    if (i >= n) return;
    float4 v = *(const float4*)(x + i);
    __nv_bfloat16 h0 = __float2bfloat16(v.x);
    __nv_bfloat16 h1 = __float2bfloat16(v.y);
    __nv_bfloat16 h2 = __float2bfloat16(v.z);
    __nv_bfloat16 h3 = __float2bfloat16(v.w);
    __nv_bfloat16 l0 = __float2bfloat16(v.x - __bfloat162float(h0));
    __nv_bfloat16 l1 = __float2bfloat16(v.y - __bfloat162float(h1));
    __nv_bfloat16 l2 = __float2bfloat16(v.z - __bfloat162float(h2));
    __nv_bfloat16 l3 = __float2bfloat16(v.w - __bfloat162float(h3));
    *(__nv_bfloat162*)(h + i)     = __nv_bfloat162(h0, h1);
    *(__nv_bfloat162*)(h + i + 2) = __nv_bfloat162(h2, h3);
    *(__nv_bfloat162*)(l + i)     = __nv_bfloat162(l0, l1);
    *(__nv_bfloat162*)(l + i + 2) = __nv_bfloat162(l2, l3);
}

// ---------------------------------------------------------------------------
// W [z][K][N] fp32  ->  Wt hi/lo [z][N][K] bf16 (transpose + split)
// ---------------------------------------------------------------------------
__global__ __launch_bounds__(256) void transpose_split_kernel(
    const float* __restrict__ W, __nv_bfloat16* __restrict__ Th,
    __nv_bfloat16* __restrict__ Tl, int K, int N)
{
    __shared__ float t[32][33];
    const int z = blockIdx.z;
    const float* Wz = W + (size_t)z * K * N;
    __nv_bfloat16* Thz = Th + (size_t)z * N * K;
    __nv_bfloat16* Tlz = Tl + (size_t)z * N * K;
    const int n0 = blockIdx.x * 32, k0 = blockIdx.y * 32;
    const int tx = threadIdx.x & 31, ty = threadIdx.x >> 5;
#pragma unroll
    for (int r = 0; r < 4; r++)
        t[ty + 8 * r][tx] = Wz[(size_t)(k0 + ty + 8 * r) * N + n0 + tx];
    __syncthreads();
#pragma unroll
    for (int r = 0; r < 4; r++) {
        int n = n0 + ty + 8 * r, k = k0 + tx;
        float v = t[tx][ty + 8 * r];
        __nv_bfloat16 h = __float2bfloat16(v);
        Thz[(size_t)n * K + k] = h;
        Tlz[(size_t)n * K + k] = __float2bfloat16(v - __bfloat162float(h));
    }
}

// ---------------------------------------------------------------------------
// bf16 split-3 GEMM on mma.sync (HMMA).  C[M,N] = A[M,K]*B[N,K]^T + bias.
// BM=BN=128, BK=32, 256 thr = 8 warps (2x4), warp tile 64x32.
// smem rows stride 80B (5x16B) -> conflict-free ldmatrix, no XOR swizzle.
// Double-buffered cp.async.
// ---------------------------------------------------------------------------
#define RS 80                       // smem row stride in bytes (32 bf16 + pad)
#define TILE_B (128 * RS)           // 10240 bytes per operand tile
#define STAGE_B (4 * TILE_B)        // Ah, Al, Bh, Bl
#define GEMM_SMEM (2 * STAGE_B)     // 81920

__global__ __launch_bounds__(256) void gemm_bf16_kernel(
    const __nv_bfloat16* __restrict__ Ah, const __nv_bfloat16* __restrict__ Al,
    const __nv_bfloat16* __restrict__ Bh, const __nv_bfloat16* __restrict__ Bl,
    long bStride,
    float* __restrict__ C, int ldc, long cStride,
    const float* __restrict__ bias, long biasStride,
    int K)
{
    extern __shared__ char smem[];
    const uint32_t sb = s2u(smem);
    const int tid = threadIdx.x, wid = tid >> 5, lane = tid & 31;
    const int wm = wid >> 2, wn = wid & 3;      // warp coords: 2 x 4
    const int mblk = blockIdx.x * 128, nblk = blockIdx.y * 128;
    const int z = blockIdx.z;
    const __nv_bfloat16* Bhz = Bh + (size_t)z * bStride;
    const __nv_bfloat16* Blz = Bl + (size_t)z * bStride;
    float* Cz = C + (size_t)z * cStride;
    const float* bz = bias + (size_t)z * biasStride;

    // per-thread global load coords: 2 chunks of 16B per tile
    const int lrow = tid >> 1;                  // 0..127
    const int lc0  = (tid & 1) * 2;             // 0 or 2 (16B units)

    auto load_stage = [&](int ks, int stg) {
        const int k0 = ks * 32;
        const uint32_t base = sb + stg * STAGE_B;
        const size_t aoff = (size_t)(mblk + lrow) * K + k0;
        const size_t boff = (size_t)(nblk + lrow) * K + k0;
        const uint32_t soff = lrow * RS;
#pragma unroll
        for (int j = 0; j < 2; j++) {
            const int c = lc0 + j;              // 16B unit within row
            cp16(base + soff + c * 16,                Ah  + aoff + c * 8);
            cp16(base + TILE_B + soff + c * 16,       Al  + aoff + c * 8);
            cp16(base + 2 * TILE_B + soff + c * 16,   Bhz + boff + c * 8);
            cp16(base + 3 * TILE_B + soff + c * 16,   Blz + boff + c * 8);
        }
        cp_commit();
    };

    // ldmatrix per-lane base offsets (bytes, within a tile)
    const uint32_t a_base = (uint32_t)(wm * 64 + (lane & 15)) * RS + (lane >> 4) * 16;
    const uint32_t b_base = (uint32_t)(wn * 32 + (lane & 7)) * RS + ((lane >> 3) & 1) * 16;

    float acc[4][4][4];
#pragma unroll
    for (int i = 0; i < 4; i++)
#pragma unroll
        for (int j = 0; j < 4; j++)
#pragma unroll
            for (int r = 0; r < 4; r++) acc[i][j][r] = 0.f;

    const int nsteps = K / 32;
    load_stage(0, 0);

    for (int s = 0; s < nsteps; s++) {
        if (s + 1 < nsteps) { load_stage(s + 1, (s + 1) & 1); cp_wait<1>(); }
        else                { cp_wait<0>(); }
        __syncthreads();

        const uint32_t stg = sb + (s & 1) * STAGE_B;
#pragma unroll
        for (int kf = 0; kf < 2; kf++) {
            const uint32_t ko = kf * 32;        // 16 bf16 = 32 bytes
            uint32_t fah[4][4], fal[4][4];
#pragma unroll
            for (int mf = 0; mf < 4; mf++) {
                ldm_x4(fah[mf][0], fah[mf][1], fah[mf][2], fah[mf][3],
                       stg + a_base + mf * (16 * RS) + ko);
                ldm_x4(fal[mf][0], fal[mf][1], fal[mf][2], fal[mf][3],
                       stg + TILE_B + a_base + mf * (16 * RS) + ko);
            }
#pragma unroll
            for (int nf = 0; nf < 4; nf++) {
                uint32_t fbh[2], fbl[2];
                ldm_x2(fbh[0], fbh[1], stg + 2 * TILE_B + b_base + nf * (8 * RS) + ko);
                ldm_x2(fbl[0], fbl[1], stg + 3 * TILE_B + b_base + nf * (8 * RS) + ko);
#pragma unroll
                for (int mf = 0; mf < 4; mf++) mma16816(acc[mf][nf], fah[mf], fbh);
#pragma unroll
                for (int mf = 0; mf < 4; mf++) mma16816(acc[mf][nf], fal[mf], fbh);
#pragma unroll
                for (int mf = 0; mf < 4; mf++) mma16816(acc[mf][nf], fah[mf], fbl);
            }
        }
        __syncthreads();
    }

    // epilogue: fragment -> global, + bias
    const int r0 = mblk + wm * 64 + (lane >> 2);
    const int c0 = nblk + wn * 32 + (lane & 3) * 2;
#pragma unroll
    for (int mf = 0; mf < 4; mf++) {
#pragma unroll
        for (int nf = 0; nf < 4; nf++) {
            const int row = r0 + mf * 16;
            const int col = c0 + nf * 8;
            const float bx = __ldg(bz + col), by = __ldg(bz + col + 1);
            float2 v0 = make_float2(acc[mf][nf][0] + bx, acc[mf][nf][1] + by);
            float2 v1 = make_float2(acc[mf][nf][2] + bx, acc[mf][nf][3] + by);
            *(float2*)(Cz + (size_t)row * ldc + col)       = v0;
            *(float2*)(Cz + (size_t)(row + 8) * ldc + col) = v1;
        }
    }
}

// ---------------------------------------------------------------------------
// Rotary (double-precision trig; safe at |angle|~2047 rad).
// ---------------------------------------------------------------------------
__global__ __launch_bounds__(128) void rotary_kernel(float* __restrict__ X, int nheads)
{
    const int p = blockIdx.x;
    const int h = blockIdx.y;
    const int i = threadIdx.x;
    float* row = X + ((long)p * nheads + h) * DH;

    const int ip = (i < 64) ? i : (i - 64);
    const double freq = exp(9.210340371976184 * ((double)ip / 64.0));
    const double ang  = (double)p / freq;
    const float s = (float)sin(ang);
    const float c = (float)cos(ang);

    const float xi = row[i];
    const float xp = (i < 64) ? row[i + 64] : row[i - 64];
    __syncthreads();
    row[i] = (i < 64) ? (xi * c - xp * s) : (xi * c + xp * s);
}

// ---------------------------------------------------------------------------
// Causal flash attention (fp32 SIMT; tensorize next round).
// ---------------------------------------------------------------------------
__global__ __launch_bounds__(256) void attn_kernel()
{
    extern __shared__ float sm[];
    float* sQ  = sm;           // [64][128]
    float* sKT = sm + 8192;    // [128][64]
    float* sV  = sm + 16384;   // [64][128]
    float* sP  = sm + 24576;   // [64][64]

    const int qb  = blockIdx.x;
    const int h   = blockIdx.y;
    const int kvh = h >> 2;
    const int tid = threadIdx.x;
    const int ty  = tid >> 4;
    const int tx  = tid & 15;
    const int q0  = qb * 64;
    const float scale = 0.08838834764831845f;

#pragma unroll
    for (int t = 0; t < 8; t++) {
        int idx = t * 256 + tid;
        int r = idx >> 5, c4 = idx & 31;
        *(float4*)(sQ + r * DH + c4 * 4) =
            *(const float4*)(g_Q + (long)(q0 + r) * DM + h * DH + c4 * 4);
    }

    float o[4][8];
    float m_i[4], l_i[4];
#pragma unroll
    for (int i = 0; i < 4; i++) {
        m_i[i] = -INFINITY; l_i[i] = 0.f;
#pragma unroll
        for (int d = 0; d < 8; d++) o[i][d] = 0.f;
    }

    for (int kb = 0; kb <= qb; kb++) {
        const int k0 = kb * 64;
        __syncthreads();
#pragma unroll
        for (int t = 0; t < 8; t++) {
            int idx = t * 256 + tid;
            {
                int j = idx & 63, c4 = idx >> 6;
                float4 kv = *(const float4*)(g_K + (long)(k0 + j) * (NKV * DH) + kvh * DH + c4 * 4);
                sKT[(c4 * 4 + 0) * 64 + j] = kv.x;
                sKT[(c4 * 4 + 1) * 64 + j] = kv.y;
                sKT[(c4 * 4 + 2) * 64 + j] = kv.z;
                sKT[(c4 * 4 + 3) * 64 + j] = kv.w;
            }
            {
                int r = idx >> 5, c4 = idx & 31;
                *(float4*)(sV + r * DH + c4 * 4) =
                    *(const float4*)(g_V + (long)(k0 + r) * (NKV * DH) + kvh * DH + c4 * 4);
            }
        }
        __syncthreads();

        float cs[4][4] = {};
#pragma unroll 4
        for (int k = 0; k < DH; k++) {
            float4 b = *(const float4*)(sKT + k * 64 + tx * 4);
#pragma unroll
            for (int ii = 0; ii < 4; ii++) {
                float a = sQ[(ty * 4 + ii) * DH + k];
                cs[ii][0] = fmaf(a, b.x, cs[ii][0]);
                cs[ii][1] = fmaf(a, b.y, cs[ii][1]);
                cs[ii][2] = fmaf(a, b.z, cs[ii][2]);
                cs[ii][3] = fmaf(a, b.w, cs[ii][3]);
            }
        }

        const bool diag = (kb == qb);
#pragma unroll
        for (int ii = 0; ii < 4; ii++) {
            const int qi = q0 + ty * 4 + ii;
#pragma unroll
            for (int jj = 0; jj < 4; jj++) {
                float sv = cs[ii][jj] * scale;
                if (diag && (k0 + tx * 4 + jj) > qi) sv = -INFINITY;
                cs[ii][jj] = sv;
            }
            float mx = fmaxf(fmaxf(cs[ii][0], cs[ii][1]), fmaxf(cs[ii][2], cs[ii][3]));
            mx = fmaxf(mx, __shfl_xor_sync(0xffffffffu, mx, 8));
            mx = fmaxf(mx, __shfl_xor_sync(0xffffffffu, mx, 4));
            mx = fmaxf(mx, __shfl_xor_sync(0xffffffffu, mx, 2));
            mx = fmaxf(mx, __shfl_xor_sync(0xffffffffu, mx, 1));
            const float mnew = fmaxf(m_i[ii], mx);
            const float corr = __expf(m_i[ii] - mnew);
            m_i[ii] = mnew;
            float rs = 0.f;
#pragma unroll
            for (int jj = 0; jj < 4; jj++) {
                float p = __expf(cs[ii][jj] - mnew);
                cs[ii][jj] = p;
                rs += p;
            }
            rs += __shfl_xor_sync(0xffffffffu, rs, 8);
            rs += __shfl_xor_sync(0xffffffffu, rs, 4);
            rs += __shfl_xor_sync(0xffffffffu, rs, 2);
            rs += __shfl_xor_sync(0xffffffffu, rs, 1);
            l_i[ii] = l_i[ii] * corr + rs;
#pragma unroll
            for (int d = 0; d < 8; d++) o[ii][d] *= corr;
            *(float4*)(sP + (ty * 4 + ii) * 64 + tx * 4) =
                make_float4(cs[ii][0], cs[ii][1], cs[ii][2], cs[ii][3]);
        }
        __syncthreads();

#pragma unroll 2
        for (int j = 0; j < 64; j++) {
            float4 v0 = *(const float4*)(sV + j * DH + tx * 8);
            float4 v1 = *(const float4*)(sV + j * DH + tx * 8 + 4);
#pragma unroll
            for (int ii = 0; ii < 4; ii++) {
                float p = sP[(ty * 4 + ii) * 64 + j];
                o[ii][0] = fmaf(p, v0.x, o[ii][0]);
                o[ii][1] = fmaf(p, v0.y, o[ii][1]);
                o[ii][2] = fmaf(p, v0.z, o[ii][2]);
                o[ii][3] = fmaf(p, v0.w, o[ii][3]);
                o[ii][4] = fmaf(p, v1.x, o[ii][4]);
                o[ii][5] = fmaf(p, v1.y, o[ii][5]);
                o[ii][6] = fmaf(p, v1.z, o[ii][6]);
                o[ii][7] = fmaf(p, v1.w, o[ii][7]);
            }
        }
    }

#pragma unroll
    for (int ii = 0; ii < 4; ii++) {
        const float inv = 1.f / l_i[ii];
        const long base = (long)(q0 + ty * 4 + ii) * DM + h * DH + tx * 8;
        *(float4*)(g_Z + base)     = make_float4(o[ii][0] * inv, o[ii][1] * inv,
                                                 o[ii][2] * inv, o[ii][3] * inv);
        *(float4*)(g_Z + base + 4) = make_float4(o[ii][4] * inv, o[ii][5] * inv,
                                                 o[ii][6] * inv, o[ii][7] * inv);
    }
}

// ---------------------------------------------------------------------------
template <typename T>
static T* symAddr(const void* sym)
{
    void* p = nullptr;
    cudaGetSymbolAddress(&p, sym);
    return (T*)p;
}

extern "C" void kernel_launch(void* const* d_in, const int* in_sizes, int n_in,
                              void* d_out, int out_size)
{
    const float* Xq = (const float*)d_in[0];
    const float* Xk = (const float*)d_in[1];
    const float* Xv = (const float*)d_in[2];
    const float* WQ = (const float*)d_in[3];
    const float* bQ = (const float*)d_in[4];
    const float* WK = (const float*)d_in[5];
    const float* bK = (const float*)d_in[6];
    const float* WV = (const float*)d_in[7];
    const float* bV = (const float*)d_in[8];
    const float* WO = (const float*)d_in[9];
    const float* bO = (const float*)d_in[10];
    float* out = (float*)d_out;

    float* Qb = symAddr<float>(g_Q);
    float* Kb = symAddr<float>(g_K);
    float* Vb = symAddr<float>(g_V);
    float* Zb = symAddr<float>(g_Z);
    __nv_bfloat16* xqh = symAddr<__nv_bfloat16>(g_xqh);
    __nv_bfloat16* xql = symAddr<__nv_bfloat16>(g_xql);
    __nv_bfloat16* xkh = symAddr<__nv_bfloat16>(g_xkh);
    __nv_bfloat16* xkl = symAddr<__nv_bfloat16>(g_xkl);
    __nv_bfloat16* xvh = symAddr<__nv_bfloat16>(g_xvh);
    __nv_bfloat16* xvl = symAddr<__nv_bfloat16>(g_xvl);
    __nv_bfloat16* zh  = symAddr<__nv_bfloat16>(g_zh);
    __nv_bfloat16* zl  = symAddr<__nv_bfloat16>(g_zl);
    __nv_bfloat16* wqh = symAddr<__nv_bfloat16>(g_wqh);
    __nv_bfloat16* wql = symAddr<__nv_bfloat16>(g_wql);
    __nv_bfloat16* wkh = symAddr<__nv_bfloat16>(g_wkh);
    __nv_bfloat16* wkl = symAddr<__nv_bfloat16>(g_wkl);
    __nv_bfloat16* wvh = symAddr<__nv_bfloat16>(g_wvh);
    __nv_bfloat16* wvl = symAddr<__nv_bfloat16>(g_wvl);
    __nv_bfloat16* woh = symAddr<__nv_bfloat16>(g_woh);
    __nv_bfloat16* wol = symAddr<__nv_bfloat16>(g_wol);

    cudaFuncSetAttribute(gemm_bf16_kernel,
                         cudaFuncAttributeMaxDynamicSharedMemorySize, GEMM_SMEM);

    const int nX = SLEN * DM;
    split_kernel<<<nX / 1024, 256>>>(Xq, xqh, xql, nX);
    split_kernel<<<nX / 1024, 256>>>(Xk, xkh, xkl, nX);
    split_kernel<<<nX / 1024, 256>>>(Xv, xvh, xvl, nX);
    transpose_split_kernel<<<dim3(DH / 32, DM / 32, NH),  256>>>(WQ, wqh, wql, DM, DH);
    transpose_split_kernel<<<dim3(DH / 32, DM / 32, NKV), 256>>>(WK, wkh, wkl, DM, DH);
    transpose_split_kernel<<<dim3(DH / 32, DM / 32, NKV), 256>>>(WV, wvh, wvl, DM, DH);
    transpose_split_kernel<<<dim3(DM / 32, DM / 32, 1),   256>>>(WO, woh, wol, DM, DM);

    // Projections: z = head index, N = 128 per head
    gemm_bf16_kernel<<<dim3(16, 1, NH), 256, GEMM_SMEM>>>(
        xqh, xql, wqh, wql, (long)DH * DM, Qb, DM, DH, bQ, DH, DM);
    gemm_bf16_kernel<<<dim3(16, 1, NKV), 256, GEMM_SMEM>>>(
        xkh, xkl, wkh, wkl, (long)DH * DM, Kb, NKV * DH, DH, bK, DH, DM);
    gemm_bf16_kernel<<<dim3(16, 1, NKV), 256, GEMM_SMEM>>>(
        xvh, xvl, wvh, wvl, (long)DH * DM, Vb, NKV * DH, DH, bV, DH, DM);

    rotary_kernel<<<dim3(SLEN, NH), 128>>>(Qb, NH);
    rotary_kernel<<<dim3(SLEN, NKV), 128>>>(Kb, NKV);

    const int attn_smem = (64 * 128 + 128 * 64 + 64 * 128 + 64 * 64) * (int)sizeof(float);
    cudaFuncSetAttribute(attn_kernel, cudaFuncAttributeMaxDynamicSharedMemorySize, attn_smem);
    attn_kernel<<<dim3(SLEN / 64, NH), 256, attn_smem>>>();

    split_kernel<<<nX / 1024, 256>>>(Zb, zh, zl, nX);
    gemm_bf16_kernel<<<dim3(16, 16, 1), 256, GEMM_SMEM>>>(
        zh, zl, woh, wol, 0, out, DM, 0, bO, 0, DM);
}

// round 6
// speedup vs baseline: 2.1807x; 1.4364x over previous
#include <cuda_runtime.h>
#include <cuda_bf16.h>
#include <cstdint>
#include <math.h>
#include <float.h>

#define SLEN 2048
#define DM   2048
#define NH   16
#define NKV  4
#define DH   128

// ---------------- scratch (__device__ globals; no allocs allowed) ----------
__device__ float g_Q[SLEN * DM];
__device__ float g_K[SLEN * NKV * DH];
__device__ float g_V[SLEN * NKV * DH];

__device__ __nv_bfloat16 g_xqh[SLEN * DM], g_xql[SLEN * DM];
__device__ __nv_bfloat16 g_xkh[SLEN * DM], g_xkl[SLEN * DM];
__device__ __nv_bfloat16 g_xvh[SLEN * DM], g_xvl[SLEN * DM];
__device__ __nv_bfloat16 g_zh [SLEN * DM], g_zl [SLEN * DM];
__device__ __nv_bfloat16 g_wqh[NH  * DH * DM], g_wql[NH  * DH * DM];
__device__ __nv_bfloat16 g_wkh[NKV * DH * DM], g_wkl[NKV * DH * DM];
__device__ __nv_bfloat16 g_wvh[NKV * DH * DM], g_wvl[NKV * DH * DM];
__device__ __nv_bfloat16 g_woh[DM * DM],       g_wol[DM * DM];
// rotary/split outputs for attention operands
__device__ __nv_bfloat16 g_qAh[SLEN * DM],        g_qAl[SLEN * DM];
__device__ __nv_bfloat16 g_kAh[SLEN * NKV * DH],  g_kAl[SLEN * NKV * DH];
__device__ __nv_bfloat16 g_vAh[SLEN * NKV * DH],  g_vAl[SLEN * NKV * DH];

// ---------------- helpers (sm_80-level features only) ----------------------
static __device__ __forceinline__ uint32_t s2u(const void* p) {
    uint32_t a;
    asm("{ .reg .u64 t; cvta.to.shared.u64 t, %1; cvt.u32.u64 %0, t; }"
        : "=r"(a) : "l"(p));
    return a;
}
static __device__ __forceinline__ void cp16(uint32_t dst, const void* src) {
    asm volatile("cp.async.cg.shared.global [%0], [%1], 16;"
                 :: "r"(dst), "l"(src) : "memory");
}
static __device__ __forceinline__ void cp_commit() {
    asm volatile("cp.async.commit_group;" ::: "memory");
}
template <int N>
static __device__ __forceinline__ void cp_wait() {
    asm volatile("cp.async.wait_group %0;" :: "n"(N) : "memory");
}
static __device__ __forceinline__ void ldm_x4(uint32_t& r0, uint32_t& r1,
                                              uint32_t& r2, uint32_t& r3, uint32_t a) {
    asm volatile("ldmatrix.sync.aligned.m8n8.x4.shared.b16 {%0,%1,%2,%3}, [%4];"
                 : "=r"(r0), "=r"(r1), "=r"(r2), "=r"(r3) : "r"(a));
}
static __device__ __forceinline__ void ldm_x4_t(uint32_t& r0, uint32_t& r1,
                                                uint32_t& r2, uint32_t& r3, uint32_t a) {
    asm volatile("ldmatrix.sync.aligned.m8n8.x4.trans.shared.b16 {%0,%1,%2,%3}, [%4];"
                 : "=r"(r0), "=r"(r1), "=r"(r2), "=r"(r3) : "r"(a));
}
static __device__ __forceinline__ void ldm_x2(uint32_t& r0, uint32_t& r1, uint32_t a) {
    asm volatile("ldmatrix.sync.aligned.m8n8.x2.shared.b16 {%0,%1}, [%2];"
                 : "=r"(r0), "=r"(r1) : "r"(a));
}
static __device__ __forceinline__ void mma16816(float* d, const uint32_t* a,
                                                const uint32_t* b) {
    asm volatile(
        "mma.sync.aligned.m16n8k16.row.col.f32.bf16.bf16.f32 "
        "{%0,%1,%2,%3}, {%4,%5,%6,%7}, {%8,%9}, {%0,%1,%2,%3};"
        : "+f"(d[0]), "+f"(d[1]), "+f"(d[2]), "+f"(d[3])
        : "r"(a[0]), "r"(a[1]), "r"(a[2]), "r"(a[3]), "r"(b[0]), "r"(b[1]));
}
static __device__ __forceinline__ uint32_t packbf(float x, float y) {
    __nv_bfloat162 t = __floats2bfloat162_rn(x, y);
    return *(uint32_t*)&t;
}

// ---------------------------------------------------------------------------
// fp32 -> (bf16 hi, bf16 lo) elementwise split.
// ---------------------------------------------------------------------------
__global__ __launch_bounds__(256) void split_kernel(
    const float* __restrict__ x, __nv_bfloat16* __restrict__ h,
    __nv_bfloat16* __restrict__ l, int n)
{
    int i = (blockIdx.x * 256 + threadIdx.x) * 4;
    if (i >= n) return;
    float4 v = *(const float4*)(x + i);
    __nv_bfloat16 h0 = __float2bfloat16(v.x);
    __nv_bfloat16 h1 = __float2bfloat16(v.y);
    __nv_bfloat16 h2 = __float2bfloat16(v.z);
    __nv_bfloat16 h3 = __float2bfloat16(v.w);
    __nv_bfloat16 l0 = __float2bfloat16(v.x - __bfloat162float(h0));
    __nv_bfloat16 l1 = __float2bfloat16(v.y - __bfloat162float(h1));
    __nv_bfloat16 l2 = __float2bfloat16(v.z - __bfloat162float(h2));
    __nv_bfloat16 l3 = __float2bfloat16(v.w - __bfloat162float(h3));
    *(__nv_bfloat162*)(h + i)     = __nv_bfloat162(h0, h1);
    *(__nv_bfloat162*)(h + i + 2) = __nv_bfloat162(h2, h3);
    *(__nv_bfloat162*)(l + i)     = __nv_bfloat162(l0, l1);
    *(__nv_bfloat162*)(l + i + 2) = __nv_bfloat162(l2, l3);
}

// ---------------------------------------------------------------------------
// W [z][K][N] fp32  ->  Wt hi/lo [z][N][K] bf16 (transpose + split)
// ---------------------------------------------------------------------------
__global__ __launch_bounds__(256) void transpose_split_kernel(
    const float* __restrict__ W, __nv_bfloat16* __restrict__ Th,
    __nv_bfloat16* __restrict__ Tl, int K, int N)
{
    __shared__ float t[32][33];
    const int z = blockIdx.z;
    const float* Wz = W + (size_t)z * K * N;
    __nv_bfloat16* Thz = Th + (size_t)z * N * K;
    __nv_bfloat16* Tlz = Tl + (size_t)z * N * K;
    const int n0 = blockIdx.x * 32, k0 = blockIdx.y * 32;
    const int tx = threadIdx.x & 31, ty = threadIdx.x >> 5;
#pragma unroll
    for (int r = 0; r < 4; r++)
        t[ty + 8 * r][tx] = Wz[(size_t)(k0 + ty + 8 * r) * N + n0 + tx];
    __syncthreads();
#pragma unroll
    for (int r = 0; r < 4; r++) {
        int n = n0 + ty + 8 * r, k = k0 + tx;
        float v = t[tx][ty + 8 * r];
        __nv_bfloat16 h = __float2bfloat16(v);
        Thz[(size_t)n * K + k] = h;
        Tlz[(size_t)n * K + k] = __float2bfloat16(v - __bfloat162float(h));
    }
}

// ---------------------------------------------------------------------------
// bf16 split-3 GEMM on mma.sync (HMMA). (unchanged from R5)
// ---------------------------------------------------------------------------
#define RS 80
#define TILE_B (128 * RS)
#define STAGE_B (4 * TILE_B)
#define GEMM_SMEM (2 * STAGE_B)

__global__ __launch_bounds__(256) void gemm_bf16_kernel(
    const __nv_bfloat16* __restrict__ Ah, const __nv_bfloat16* __restrict__ Al,
    const __nv_bfloat16* __restrict__ Bh, const __nv_bfloat16* __restrict__ Bl,
    long bStride,
    float* __restrict__ C, int ldc, long cStride,
    const float* __restrict__ bias, long biasStride,
    int K)
{
    extern __shared__ char smem[];
    const uint32_t sb = s2u(smem);
    const int tid = threadIdx.x, wid = tid >> 5, lane = tid & 31;
    const int wm = wid >> 2, wn = wid & 3;
    const int mblk = blockIdx.x * 128, nblk = blockIdx.y * 128;
    const int z = blockIdx.z;
    const __nv_bfloat16* Bhz = Bh + (size_t)z * bStride;
    const __nv_bfloat16* Blz = Bl + (size_t)z * bStride;
    float* Cz = C + (size_t)z * cStride;
    const float* bz = bias + (size_t)z * biasStride;

    const int lrow = tid >> 1;
    const int lc0  = (tid & 1) * 2;

    auto load_stage = [&](int ks, int stg) {
        const int k0 = ks * 32;
        const uint32_t base = sb + stg * STAGE_B;
        const size_t aoff = (size_t)(mblk + lrow) * K + k0;
        const size_t boff = (size_t)(nblk + lrow) * K + k0;
        const uint32_t soff = lrow * RS;
#pragma unroll
        for (int j = 0; j < 2; j++) {
            const int c = lc0 + j;
            cp16(base + soff + c * 16,                Ah  + aoff + c * 8);
            cp16(base + TILE_B + soff + c * 16,       Al  + aoff + c * 8);
            cp16(base + 2 * TILE_B + soff + c * 16,   Bhz + boff + c * 8);
            cp16(base + 3 * TILE_B + soff + c * 16,   Blz + boff + c * 8);
        }
        cp_commit();
    };

    const uint32_t a_base = (uint32_t)(wm * 64 + (lane & 15)) * RS + (lane >> 4) * 16;
    const uint32_t b_base = (uint32_t)(wn * 32 + (lane & 7)) * RS + ((lane >> 3) & 1) * 16;

    float acc[4][4][4];
#pragma unroll
    for (int i = 0; i < 4; i++)
#pragma unroll
        for (int j = 0; j < 4; j++)
#pragma unroll
            for (int r = 0; r < 4; r++) acc[i][j][r] = 0.f;

    const int nsteps = K / 32;
    load_stage(0, 0);

    for (int s = 0; s < nsteps; s++) {
        if (s + 1 < nsteps) { load_stage(s + 1, (s + 1) & 1); cp_wait<1>(); }
        else                { cp_wait<0>(); }
        __syncthreads();

        const uint32_t stg = sb + (s & 1) * STAGE_B;
#pragma unroll
        for (int kf = 0; kf < 2; kf++) {
            const uint32_t ko = kf * 32;
            uint32_t fah[4][4], fal[4][4];
#pragma unroll
            for (int mf = 0; mf < 4; mf++) {
                ldm_x4(fah[mf][0], fah[mf][1], fah[mf][2], fah[mf][3],
                       stg + a_base + mf * (16 * RS) + ko);
                ldm_x4(fal[mf][0], fal[mf][1], fal[mf][2], fal[mf][3],
                       stg + TILE_B + a_base + mf * (16 * RS) + ko);
            }
#pragma unroll
            for (int nf = 0; nf < 4; nf++) {
                uint32_t fbh[2], fbl[2];
                ldm_x2(fbh[0], fbh[1], stg + 2 * TILE_B + b_base + nf * (8 * RS) + ko);
                ldm_x2(fbl[0], fbl[1], stg + 3 * TILE_B + b_base + nf * (8 * RS) + ko);
#pragma unroll
                for (int mf = 0; mf < 4; mf++) mma16816(acc[mf][nf], fah[mf], fbh);
#pragma unroll
                for (int mf = 0; mf < 4; mf++) mma16816(acc[mf][nf], fal[mf], fbh);
#pragma unroll
                for (int mf = 0; mf < 4; mf++) mma16816(acc[mf][nf], fah[mf], fbl);
            }
        }
        __syncthreads();
    }

    const int r0 = mblk + wm * 64 + (lane >> 2);
    const int c0 = nblk + wn * 32 + (lane & 3) * 2;
#pragma unroll
    for (int mf = 0; mf < 4; mf++) {
#pragma unroll
        for (int nf = 0; nf < 4; nf++) {
            const int row = r0 + mf * 16;
            const int col = c0 + nf * 8;
            const float bx = __ldg(bz + col), by = __ldg(bz + col + 1);
            float2 v0 = make_float2(acc[mf][nf][0] + bx, acc[mf][nf][1] + by);
            float2 v1 = make_float2(acc[mf][nf][2] + bx, acc[mf][nf][3] + by);
            *(float2*)(Cz + (size_t)row * ldc + col)       = v0;
            *(float2*)(Cz + (size_t)(row + 8) * ldc + col) = v1;
        }
    }
}

// ---------------------------------------------------------------------------
// Rotary + bf16 hi/lo split (fused).  Double-precision trig.
// ---------------------------------------------------------------------------
__global__ __launch_bounds__(128) void rotary_split_kernel(
    const float* __restrict__ X, __nv_bfloat16* __restrict__ H,
    __nv_bfloat16* __restrict__ L, int nheads)
{
    const int p = blockIdx.x;
    const int h = blockIdx.y;
    const int i = threadIdx.x;
    const size_t base = ((size_t)p * nheads + h) * DH;
    const float* row = X + base;

    const int ip = (i < 64) ? i : (i - 64);
    const double freq = exp(9.210340371976184 * ((double)ip / 64.0));
    const double ang  = (double)p / freq;
    const float s = (float)sin(ang);
    const float c = (float)cos(ang);

    const float xi = row[i];
    const float xp = (i < 64) ? row[i + 64] : row[i - 64];
    const float v = (i < 64) ? (xi * c - xp * s) : (xi * c + xp * s);
    const __nv_bfloat16 hv = __float2bfloat16(v);
    H[base + i] = hv;
    L[base + i] = __float2bfloat16(v - __bfloat162float(hv));
}

// ---------------------------------------------------------------------------
// Flash attention on mma.sync bf16 split-3 (QK and PV).
// BQ=BK=64, D=128, 128 threads (4 warps; warp = 16 q-rows).
// smem: Q hi/lo (static) + double-buffered K/V hi/lo tiles.  Row stride 272B.
// Writes zh/zl bf16 directly.
// ---------------------------------------------------------------------------
#define ARS 272                      // attn smem row stride (256 + 16 pad)
#define AQT (64 * ARS)               // 17408 per operand tile
#define A_SQH 0
#define A_SQL AQT
#define A_KV0 (2 * AQT)              // 34816
#define A_STG (4 * AQT)              // 69632 per stage (Kh,Kl,Vh,Vl)
#define ATTN_SMEM (A_KV0 + 2 * A_STG)  // 174080

__global__ __launch_bounds__(128) void attn_mma_kernel()
{
    extern __shared__ char smem[];
    const uint32_t sb = s2u(smem);
    const int tid  = threadIdx.x;
    const int lane = tid & 31;
    const int wq   = tid >> 5;                 // warp -> q rows [wq*16, +16)
    const int qb   = 31 - blockIdx.x;          // heavy CTAs first
    const int h    = blockIdx.y;
    const int kvh  = h >> 2;
    const int q0   = qb * 64;

    // ---- load Q hi/lo tiles ----
    {
        const int row = tid >> 1;
        const int cb  = (tid & 1) * 8;
        const size_t goff = (size_t)(q0 + row) * DM + h * DH;
#pragma unroll
        for (int j = 0; j < 8; j++) {
            const int c = cb + j;
            cp16(sb + A_SQH + row * ARS + c * 16, g_qAh + goff + c * 8);
            cp16(sb + A_SQL + row * ARS + c * 16, g_qAl + goff + c * 8);
        }
        cp_commit();
    }

    auto load_kv = [&](int kb, int stg) {
        const uint32_t base = sb + A_KV0 + stg * A_STG;
        const int row = tid >> 1;
        const int cb  = (tid & 1) * 8;
        const size_t goff = (size_t)(kb * 64 + row) * (NKV * DH) + kvh * DH;
#pragma unroll
        for (int j = 0; j < 8; j++) {
            const int c = cb + j;
            cp16(base + 0 * AQT + row * ARS + c * 16, g_kAh + goff + c * 8);
            cp16(base + 1 * AQT + row * ARS + c * 16, g_kAl + goff + c * 8);
            cp16(base + 2 * AQT + row * ARS + c * 16, g_vAh + goff + c * 8);
            cp16(base + 3 * AQT + row * ARS + c * 16, g_vAl + goff + c * 8);
        }
        cp_commit();
    };
    load_kv(0, 0);

    float o[16][4];
#pragma unroll
    for (int i = 0; i < 16; i++)
#pragma unroll
        for (int r = 0; r < 4; r++) o[i][r] = 0.f;
    float m0 = -INFINITY, m1 = -INFINITY, l0 = 0.f, l1 = 0.f;

    // fragment address components (within a tile, bytes)
    const uint32_t frag_row = (uint32_t)((lane & 7) + ((lane >> 3) & 1) * 8) * ARS;
    const uint32_t frag_col = ((lane >> 4) & 1) * 16;
    const float SCL = 0.08838834764831845f * 1.4426950408889634f; // scale*log2e

    for (int kb = 0; kb <= qb; kb++) {
        if (kb < qb) { load_kv(kb + 1, (kb + 1) & 1); cp_wait<1>(); }
        else         { cp_wait<0>(); }
        __syncthreads();

        const uint32_t skv = sb + A_KV0 + (kb & 1) * A_STG;

        // ---- S = Q K^T (split-3) ----
        float sc[8][4];
#pragma unroll
        for (int i = 0; i < 8; i++)
#pragma unroll
            for (int r = 0; r < 4; r++) sc[i][r] = 0.f;

#pragma unroll
        for (int ks = 0; ks < 8; ks++) {
            const uint32_t qoff = (uint32_t)(wq * 16) * ARS + frag_row + ks * 32 + frag_col;
            uint32_t qh[4], ql[4];
            ldm_x4(qh[0], qh[1], qh[2], qh[3], sb + A_SQH + qoff);
            ldm_x4(ql[0], ql[1], ql[2], ql[3], sb + A_SQL + qoff);
#pragma unroll
            for (int np = 0; np < 4; np++) {
                const uint32_t koff = (uint32_t)(np * 16) * ARS + frag_row + ks * 32 + frag_col;
                uint32_t kh[4], kl[4];
                ldm_x4(kh[0], kh[1], kh[2], kh[3], skv + 0 * AQT + koff);
                ldm_x4(kl[0], kl[1], kl[2], kl[3], skv + 1 * AQT + koff);
                uint32_t bh0[2] = {kh[0], kh[2]}, bh1[2] = {kh[1], kh[3]};
                uint32_t bl0[2] = {kl[0], kl[2]}, bl1[2] = {kl[1], kl[3]};
                mma16816(sc[2 * np],     qh, bh0);
                mma16816(sc[2 * np],     qh, bl0);
                mma16816(sc[2 * np],     ql, bh0);
                mma16816(sc[2 * np + 1], qh, bh1);
                mma16816(sc[2 * np + 1], qh, bl1);
                mma16816(sc[2 * np + 1], ql, bh1);
            }
        }

        // ---- online softmax (t = s*scale*log2e units) ----
        const int r0 = wq * 16 + (lane >> 2);
        const int r1 = r0 + 8;
        const bool diag = (kb == qb);
        float mx0 = -INFINITY, mx1 = -INFINITY;
#pragma unroll
        for (int nf = 0; nf < 8; nf++) {
            float t0 = sc[nf][0] * SCL, t1 = sc[nf][1] * SCL;
            float t2 = sc[nf][2] * SCL, t3 = sc[nf][3] * SCL;
            if (diag) {
                const int col = nf * 8 + (lane & 3) * 2;
                if (col     > r0) t0 = -INFINITY;
                if (col + 1 > r0) t1 = -INFINITY;
                if (col     > r1) t2 = -INFINITY;
                if (col + 1 > r1) t3 = -INFINITY;
            }
            sc[nf][0] = t0; sc[nf][1] = t1; sc[nf][2] = t2; sc[nf][3] = t3;
            mx0 = fmaxf(mx0, fmaxf(t0, t1));
            mx1 = fmaxf(mx1, fmaxf(t2, t3));
        }
        mx0 = fmaxf(mx0, __shfl_xor_sync(0xffffffffu, mx0, 1));
        mx0 = fmaxf(mx0, __shfl_xor_sync(0xffffffffu, mx0, 2));
        mx1 = fmaxf(mx1, __shfl_xor_sync(0xffffffffu, mx1, 1));
        mx1 = fmaxf(mx1, __shfl_xor_sync(0xffffffffu, mx1, 2));
        const float mn0 = fmaxf(m0, mx0), mn1 = fmaxf(m1, mx1);
        const float corr0 = exp2f(m0 - mn0), corr1 = exp2f(m1 - mn1);
        m0 = mn0; m1 = mn1;

        float rs0 = 0.f, rs1 = 0.f;
#pragma unroll
        for (int nf = 0; nf < 8; nf++) {
            float p0 = exp2f(sc[nf][0] - mn0);
            float p1 = exp2f(sc[nf][1] - mn0);
            float p2 = exp2f(sc[nf][2] - mn1);
            float p3 = exp2f(sc[nf][3] - mn1);
            sc[nf][0] = p0; sc[nf][1] = p1; sc[nf][2] = p2; sc[nf][3] = p3;
            rs0 += p0 + p1; rs1 += p2 + p3;
        }
        rs0 += __shfl_xor_sync(0xffffffffu, rs0, 1);
        rs0 += __shfl_xor_sync(0xffffffffu, rs0, 2);
        rs1 += __shfl_xor_sync(0xffffffffu, rs1, 1);
        rs1 += __shfl_xor_sync(0xffffffffu, rs1, 2);
        l0 = l0 * corr0 + rs0;
        l1 = l1 * corr1 + rs1;
#pragma unroll
        for (int i = 0; i < 16; i++) {
            o[i][0] *= corr0; o[i][1] *= corr0;
            o[i][2] *= corr1; o[i][3] *= corr1;
        }

        // ---- pack P into A fragments (hi + residual lo) ----
        uint32_t pAh[4][4], pAl[4][4];
#pragma unroll
        for (int kg = 0; kg < 4; kg++) {
            const float c0 = sc[2 * kg][0], c1 = sc[2 * kg][1];
            const float c2 = sc[2 * kg][2], c3 = sc[2 * kg][3];
            const float d0 = sc[2 * kg + 1][0], d1 = sc[2 * kg + 1][1];
            const float d2 = sc[2 * kg + 1][2], d3 = sc[2 * kg + 1][3];
            pAh[kg][0] = packbf(c0, c1);
            pAh[kg][1] = packbf(c2, c3);
            pAh[kg][2] = packbf(d0, d1);
            pAh[kg][3] = packbf(d2, d3);
            pAl[kg][0] = packbf(c0 - __bfloat162float(__float2bfloat16(c0)),
                                c1 - __bfloat162float(__float2bfloat16(c1)));
            pAl[kg][1] = packbf(c2 - __bfloat162float(__float2bfloat16(c2)),
                                c3 - __bfloat162float(__float2bfloat16(c3)));
            pAl[kg][2] = packbf(d0 - __bfloat162float(__float2bfloat16(d0)),
                                d1 - __bfloat162float(__float2bfloat16(d1)));
            pAl[kg][3] = packbf(d2 - __bfloat162float(__float2bfloat16(d2)),
                                d3 - __bfloat162float(__float2bfloat16(d3)));
        }

        // ---- O += P V (split-3), V^T via ldmatrix.trans ----
#pragma unroll
        for (int dg = 0; dg < 8; dg++) {
#pragma unroll
            for (int kg = 0; kg < 4; kg++) {
                const uint32_t voff = (uint32_t)(kg * 16) * ARS + frag_row + dg * 32 + frag_col;
                uint32_t vh[4], vl[4];
                ldm_x4_t(vh[0], vh[1], vh[2], vh[3], skv + 2 * AQT + voff);
                ldm_x4_t(vl[0], vl[1], vl[2], vl[3], skv + 3 * AQT + voff);
                uint32_t bh0[2] = {vh[0], vh[1]}, bh1[2] = {vh[2], vh[3]};
                uint32_t bl0[2] = {vl[0], vl[1]}, bl1[2] = {vl[2], vl[3]};
                mma16816(o[2 * dg],     pAh[kg], bh0);
                mma16816(o[2 * dg],     pAh[kg], bl0);
                mma16816(o[2 * dg],     pAl[kg], bh0);
                mma16816(o[2 * dg + 1], pAh[kg], bh1);
                mma16816(o[2 * dg + 1], pAh[kg], bl1);
                mma16816(o[2 * dg + 1], pAl[kg], bh1);
            }
        }
        __syncthreads();
    }

    // ---- epilogue: normalize, split to bf16 hi/lo, store ----
    const float inv0 = 1.f / l0, inv1 = 1.f / l1;
    const int rg0 = q0 + wq * 16 + (lane >> 2);
#pragma unroll
    for (int nf = 0; nf < 16; nf++) {
        const int col = h * DH + nf * 8 + (lane & 3) * 2;
        const float a0 = o[nf][0] * inv0, a1 = o[nf][1] * inv0;
        const float a2 = o[nf][2] * inv1, a3 = o[nf][3] * inv1;
        const __nv_bfloat16 h0 = __float2bfloat16(a0), h1 = __float2bfloat16(a1);
        const __nv_bfloat16 h2 = __float2bfloat16(a2), h3 = __float2bfloat16(a3);
        const size_t b0 = (size_t)rg0 * DM + col;
        const size_t b1 = (size_t)(rg0 + 8) * DM + col;
        *(__nv_bfloat162*)(g_zh + b0) = __nv_bfloat162(h0, h1);
        *(__nv_bfloat162*)(g_zh + b1) = __nv_bfloat162(h2, h3);
        *(__nv_bfloat162*)(g_zl + b0) =
            __nv_bfloat162(__float2bfloat16(a0 - __bfloat162float(h0)),
                           __float2bfloat16(a1 - __bfloat162float(h1)));
        *(__nv_bfloat162*)(g_zl + b1) =
            __nv_bfloat162(__float2bfloat16(a2 - __bfloat162float(h2)),
                           __float2bfloat16(a3 - __bfloat162float(h3)));
    }
}

// ---------------------------------------------------------------------------
template <typename T>
static T* symAddr(const void* sym)
{
    void* p = nullptr;
    cudaGetSymbolAddress(&p, sym);
    return (T*)p;
}

extern "C" void kernel_launch(void* const* d_in, const int* in_sizes, int n_in,
                              void* d_out, int out_size)
{
    const float* Xq = (const float*)d_in[0];
    const float* Xk = (const float*)d_in[1];
    const float* Xv = (const float*)d_in[2];
    const float* WQ = (const float*)d_in[3];
    const float* bQ = (const float*)d_in[4];
    const float* WK = (const float*)d_in[5];
    const float* bK = (const float*)d_in[6];
    const float* WV = (const float*)d_in[7];
    const float* bV = (const float*)d_in[8];
    const float* WO = (const float*)d_in[9];
    const float* bO = (const float*)d_in[10];
    float* out = (float*)d_out;

    float* Qb = symAddr<float>(g_Q);
    float* Kb = symAddr<float>(g_K);
    float* Vb = symAddr<float>(g_V);
    __nv_bfloat16* xqh = symAddr<__nv_bfloat16>(g_xqh);
    __nv_bfloat16* xql = symAddr<__nv_bfloat16>(g_xql);
    __nv_bfloat16* xkh = symAddr<__nv_bfloat16>(g_xkh);
    __nv_bfloat16* xkl = symAddr<__nv_bfloat16>(g_xkl);
    __nv_bfloat16* xvh = symAddr<__nv_bfloat16>(g_xvh);
    __nv_bfloat16* xvl = symAddr<__nv_bfloat16>(g_xvl);
    __nv_bfloat16* zh  = symAddr<__nv_bfloat16>(g_zh);
    __nv_bfloat16* zl  = symAddr<__nv_bfloat16>(g_zl);
    __nv_bfloat16* wqh = symAddr<__nv_bfloat16>(g_wqh);
    __nv_bfloat16* wql = symAddr<__nv_bfloat16>(g_wql);
    __nv_bfloat16* wkh = symAddr<__nv_bfloat16>(g_wkh);
    __nv_bfloat16* wkl = symAddr<__nv_bfloat16>(g_wkl);
    __nv_bfloat16* wvh = symAddr<__nv_bfloat16>(g_wvh);
    __nv_bfloat16* wvl = symAddr<__nv_bfloat16>(g_wvl);
    __nv_bfloat16* woh = symAddr<__nv_bfloat16>(g_woh);
    __nv_bfloat16* wol = symAddr<__nv_bfloat16>(g_wol);
    __nv_bfloat16* qAh = symAddr<__nv_bfloat16>(g_qAh);
    __nv_bfloat16* qAl = symAddr<__nv_bfloat16>(g_qAl);
    __nv_bfloat16* kAh = symAddr<__nv_bfloat16>(g_kAh);
    __nv_bfloat16* kAl = symAddr<__nv_bfloat16>(g_kAl);
    __nv_bfloat16* vAh = symAddr<__nv_bfloat16>(g_vAh);
    __nv_bfloat16* vAl = symAddr<__nv_bfloat16>(g_vAl);

    cudaFuncSetAttribute(gemm_bf16_kernel,
                         cudaFuncAttributeMaxDynamicSharedMemorySize, GEMM_SMEM);
    cudaFuncSetAttribute(attn_mma_kernel,
                         cudaFuncAttributeMaxDynamicSharedMemorySize, ATTN_SMEM);

    const int nX = SLEN * DM;
    split_kernel<<<nX / 1024, 256>>>(Xq, xqh, xql, nX);
    split_kernel<<<nX / 1024, 256>>>(Xk, xkh, xkl, nX);
    split_kernel<<<nX / 1024, 256>>>(Xv, xvh, xvl, nX);
    transpose_split_kernel<<<dim3(DH / 32, DM / 32, NH),  256>>>(WQ, wqh, wql, DM, DH);
    transpose_split_kernel<<<dim3(DH / 32, DM / 32, NKV), 256>>>(WK, wkh, wkl, DM, DH);
    transpose_split_kernel<<<dim3(DH / 32, DM / 32, NKV), 256>>>(WV, wvh, wvl, DM, DH);
    transpose_split_kernel<<<dim3(DM / 32, DM / 32, 1),   256>>>(WO, woh, wol, DM, DM);

    gemm_bf16_kernel<<<dim3(16, 1, NH), 256, GEMM_SMEM>>>(
        xqh, xql, wqh, wql, (long)DH * DM, Qb, DM, DH, bQ, DH, DM);
    gemm_bf16_kernel<<<dim3(16, 1, NKV), 256, GEMM_SMEM>>>(
        xkh, xkl, wkh, wkl, (long)DH * DM, Kb, NKV * DH, DH, bK, DH, DM);
    gemm_bf16_kernel<<<dim3(16, 1, NKV), 256, GEMM_SMEM>>>(
        xvh, xvl, wvh, wvl, (long)DH * DM, Vb, NKV * DH, DH, bV, DH, DM);

    rotary_split_kernel<<<dim3(SLEN, NH),  128>>>(Qb, qAh, qAl, NH);
    rotary_split_kernel<<<dim3(SLEN, NKV), 128>>>(Kb, kAh, kAl, NKV);
    split_kernel<<<(SLEN * NKV * DH) / 1024, 256>>>(Vb, vAh, vAl, SLEN * NKV * DH);

    attn_mma_kernel<<<dim3(32, NH), 128, ATTN_SMEM>>>();

    gemm_bf16_kernel<<<dim3(16, 16, 1), 256, GEMM_SMEM>>>(
        zh, zl, woh, wol, 0, out, DM, 0, bO, 0, DM);
}

// round 7
// speedup vs baseline: 2.4122x; 1.1062x over previous
#include <cuda_runtime.h>
#include <cuda_bf16.h>
#include <cstdint>
#include <math.h>
#include <float.h>

#define SLEN 2048
#define DM   2048
#define NH   16
#define NKV  4
#define DH   128

// ---------------- scratch (__device__ globals; no allocs allowed) ----------
__device__ float g_Q[SLEN * DM];
__device__ float g_K[SLEN * NKV * DH];
__device__ float2 g_rot[SLEN * 64];

__device__ __nv_bfloat16 g_xqh[SLEN * DM], g_xql[SLEN * DM];
__device__ __nv_bfloat16 g_xkh[SLEN * DM], g_xkl[SLEN * DM];
__device__ __nv_bfloat16 g_xvh[SLEN * DM], g_xvl[SLEN * DM];
__device__ __nv_bfloat16 g_zh [SLEN * DM], g_zl [SLEN * DM];
__device__ __nv_bfloat16 g_wqh[NH  * DH * DM], g_wql[NH  * DH * DM];
__device__ __nv_bfloat16 g_wkh[NKV * DH * DM], g_wkl[NKV * DH * DM];
__device__ __nv_bfloat16 g_wvh[NKV * DH * DM], g_wvl[NKV * DH * DM];
__device__ __nv_bfloat16 g_woh[DM * DM],       g_wol[DM * DM];
// attention operands (post-rotary / post-projection splits)
__device__ __nv_bfloat16 g_qAh[SLEN * DM],        g_qAl[SLEN * DM];
__device__ __nv_bfloat16 g_kAh[SLEN * NKV * DH],  g_kAl[SLEN * NKV * DH];
__device__ __nv_bfloat16 g_vAh[SLEN * NKV * DH],  g_vAl[SLEN * NKV * DH];

// ---------------- helpers (sm_80-level features only) ----------------------
static __device__ __forceinline__ uint32_t s2u(const void* p) {
    uint32_t a;
    asm("{ .reg .u64 t; cvta.to.shared.u64 t, %1; cvt.u32.u64 %0, t; }"
        : "=r"(a) : "l"(p));
    return a;
}
static __device__ __forceinline__ void cp16(uint32_t dst, const void* src) {
    asm volatile("cp.async.cg.shared.global [%0], [%1], 16;"
                 :: "r"(dst), "l"(src) : "memory");
}
static __device__ __forceinline__ void cp_commit() {
    asm volatile("cp.async.commit_group;" ::: "memory");
}
template <int N>
static __device__ __forceinline__ void cp_wait() {
    asm volatile("cp.async.wait_group %0;" :: "n"(N) : "memory");
}
static __device__ __forceinline__ void ldm_x4(uint32_t& r0, uint32_t& r1,
                                              uint32_t& r2, uint32_t& r3, uint32_t a) {
    asm volatile("ldmatrix.sync.aligned.m8n8.x4.shared.b16 {%0,%1,%2,%3}, [%4];"
                 : "=r"(r0), "=r"(r1), "=r"(r2), "=r"(r3) : "r"(a));
}
static __device__ __forceinline__ void ldm_x4_t(uint32_t& r0, uint32_t& r1,
                                                uint32_t& r2, uint32_t& r3, uint32_t a) {
    asm volatile("ldmatrix.sync.aligned.m8n8.x4.trans.shared.b16 {%0,%1,%2,%3}, [%4];"
                 : "=r"(r0), "=r"(r1), "=r"(r2), "=r"(r3) : "r"(a));
}
static __device__ __forceinline__ void ldm_x2(uint32_t& r0, uint32_t& r1, uint32_t a) {
    asm volatile("ldmatrix.sync.aligned.m8n8.x2.shared.b16 {%0,%1}, [%2];"
                 : "=r"(r0), "=r"(r1) : "r"(a));
}
static __device__ __forceinline__ void mma16816(float* d, const uint32_t* a,
                                                const uint32_t* b) {
    asm volatile(
        "mma.sync.aligned.m16n8k16.row.col.f32.bf16.bf16.f32 "
        "{%0,%1,%2,%3}, {%4,%5,%6,%7}, {%8,%9}, {%0,%1,%2,%3};"
        : "+f"(d[0]), "+f"(d[1]), "+f"(d[2]), "+f"(d[3])
        : "r"(a[0]), "r"(a[1]), "r"(a[2]), "r"(a[3]), "r"(b[0]), "r"(b[1]));
}
static __device__ __forceinline__ uint32_t packbf(float x, float y) {
    __nv_bfloat162 t = __floats2bfloat162_rn(x, y);
    return *(uint32_t*)&t;
}

// ---------------------------------------------------------------------------
// fp32 -> (bf16 hi, bf16 lo) elementwise split.
// ---------------------------------------------------------------------------
__global__ __launch_bounds__(256) void split_kernel(
    const float* __restrict__ x, __nv_bfloat16* __restrict__ h,
    __nv_bfloat16* __restrict__ l, int n)
{
    int i = (blockIdx.x * 256 + threadIdx.x) * 4;
    if (i >= n) return;
    float4 v = *(const float4*)(x + i);
    __nv_bfloat16 h0 = __float2bfloat16(v.x);
    __nv_bfloat16 h1 = __float2bfloat16(v.y);
    __nv_bfloat16 h2 = __float2bfloat16(v.z);
    __nv_bfloat16 h3 = __float2bfloat16(v.w);
    __nv_bfloat16 l0 = __float2bfloat16(v.x - __bfloat162float(h0));
    __nv_bfloat16 l1 = __float2bfloat16(v.y - __bfloat162float(h1));
    __nv_bfloat16 l2 = __float2bfloat16(v.z - __bfloat162float(h2));
    __nv_bfloat16 l3 = __float2bfloat16(v.w - __bfloat162float(h3));
    *(__nv_bfloat162*)(h + i)     = __nv_bfloat162(h0, h1);
    *(__nv_bfloat162*)(h + i + 2) = __nv_bfloat162(h2, h3);
    *(__nv_bfloat162*)(l + i)     = __nv_bfloat162(l0, l1);
    *(__nv_bfloat162*)(l + i + 2) = __nv_bfloat162(l2, l3);
}

// ---------------------------------------------------------------------------
// W [z][K][N] fp32  ->  Wt hi/lo [z][N][K] bf16 (transpose + split)
// ---------------------------------------------------------------------------
__global__ __launch_bounds__(256) void transpose_split_kernel(
    const float* __restrict__ W, __nv_bfloat16* __restrict__ Th,
    __nv_bfloat16* __restrict__ Tl, int K, int N)
{
    __shared__ float t[32][33];
    const int z = blockIdx.z;
    const float* Wz = W + (size_t)z * K * N;
    __nv_bfloat16* Thz = Th + (size_t)z * N * K;
    __nv_bfloat16* Tlz = Tl + (size_t)z * N * K;
    const int n0 = blockIdx.x * 32, k0 = blockIdx.y * 32;
    const int tx = threadIdx.x & 31, ty = threadIdx.x >> 5;
#pragma unroll
    for (int r = 0; r < 4; r++)
        t[ty + 8 * r][tx] = Wz[(size_t)(k0 + ty + 8 * r) * N + n0 + tx];
    __syncthreads();
#pragma unroll
    for (int r = 0; r < 4; r++) {
        int n = n0 + ty + 8 * r, k = k0 + tx;
        float v = t[tx][ty + 8 * r];
        __nv_bfloat16 h = __float2bfloat16(v);
        Thz[(size_t)n * K + k] = h;
        Tlz[(size_t)n * K + k] = __float2bfloat16(v - __bfloat162float(h));
    }
}

// ---------------------------------------------------------------------------
// bf16 split-3 GEMM on mma.sync (HMMA).  OUTBF=0: fp32 C.  OUTBF=1: bf16 hi/lo.
// ---------------------------------------------------------------------------
#define RS 80
#define TILE_B (128 * RS)
#define STAGE_B (4 * TILE_B)
#define GEMM_SMEM (2 * STAGE_B)

template <int OUTBF>
__global__ __launch_bounds__(256) void gemm_bf16_kernel(
    const __nv_bfloat16* __restrict__ Ah, const __nv_bfloat16* __restrict__ Al,
    const __nv_bfloat16* __restrict__ Bh, const __nv_bfloat16* __restrict__ Bl,
    long bStride,
    float* __restrict__ C, __nv_bfloat16* __restrict__ Ch,
    __nv_bfloat16* __restrict__ Cl,
    int ldc, long cStride,
    const float* __restrict__ bias, long biasStride,
    int K)
{
    extern __shared__ char smem[];
    const uint32_t sb = s2u(smem);
    const int tid = threadIdx.x, wid = tid >> 5, lane = tid & 31;
    const int wm = wid >> 2, wn = wid & 3;
    const int mblk = blockIdx.x * 128, nblk = blockIdx.y * 128;
    const int z = blockIdx.z;
    const __nv_bfloat16* Bhz = Bh + (size_t)z * bStride;
    const __nv_bfloat16* Blz = Bl + (size_t)z * bStride;
    const float* bz = bias + (size_t)z * biasStride;

    const int lrow = tid >> 1;
    const int lc0  = (tid & 1) * 2;

    auto load_stage = [&](int ks, int stg) {
        const int k0 = ks * 32;
        const uint32_t base = sb + stg * STAGE_B;
        const size_t aoff = (size_t)(mblk + lrow) * K + k0;
        const size_t boff = (size_t)(nblk + lrow) * K + k0;
        const uint32_t soff = lrow * RS;
#pragma unroll
        for (int j = 0; j < 2; j++) {
            const int c = lc0 + j;
            cp16(base + soff + c * 16,                Ah  + aoff + c * 8);
            cp16(base + TILE_B + soff + c * 16,       Al  + aoff + c * 8);
            cp16(base + 2 * TILE_B + soff + c * 16,   Bhz + boff + c * 8);
            cp16(base + 3 * TILE_B + soff + c * 16,   Blz + boff + c * 8);
        }
        cp_commit();
    };

    const uint32_t a_base = (uint32_t)(wm * 64 + (lane & 15)) * RS + (lane >> 4) * 16;
    const uint32_t b_base = (uint32_t)(wn * 32 + (lane & 7)) * RS + ((lane >> 3) & 1) * 16;

    float acc[4][4][4];
#pragma unroll
    for (int i = 0; i < 4; i++)
#pragma unroll
        for (int j = 0; j < 4; j++)
#pragma unroll
            for (int r = 0; r < 4; r++) acc[i][j][r] = 0.f;

    const int nsteps = K / 32;
    load_stage(0, 0);

    for (int s = 0; s < nsteps; s++) {
        if (s + 1 < nsteps) { load_stage(s + 1, (s + 1) & 1); cp_wait<1>(); }
        else                { cp_wait<0>(); }
        __syncthreads();

        const uint32_t stg = sb + (s & 1) * STAGE_B;
#pragma unroll
        for (int kf = 0; kf < 2; kf++) {
            const uint32_t ko = kf * 32;
            uint32_t fah[4][4], fal[4][4];
#pragma unroll
            for (int mf = 0; mf < 4; mf++) {
                ldm_x4(fah[mf][0], fah[mf][1], fah[mf][2], fah[mf][3],
                       stg + a_base + mf * (16 * RS) + ko);
                ldm_x4(fal[mf][0], fal[mf][1], fal[mf][2], fal[mf][3],
                       stg + TILE_B + a_base + mf * (16 * RS) + ko);
            }
#pragma unroll
            for (int nf = 0; nf < 4; nf++) {
                uint32_t fbh[2], fbl[2];
                ldm_x2(fbh[0], fbh[1], stg + 2 * TILE_B + b_base + nf * (8 * RS) + ko);
                ldm_x2(fbl[0], fbl[1], stg + 3 * TILE_B + b_base + nf * (8 * RS) + ko);
#pragma unroll
                for (int mf = 0; mf < 4; mf++) mma16816(acc[mf][nf], fah[mf], fbh);
#pragma unroll
                for (int mf = 0; mf < 4; mf++) mma16816(acc[mf][nf], fal[mf], fbh);
#pragma unroll
                for (int mf = 0; mf < 4; mf++) mma16816(acc[mf][nf], fah[mf], fbl);
            }
        }
        __syncthreads();
    }

    const int r0 = mblk + wm * 64 + (lane >> 2);
    const int c0 = nblk + wn * 32 + (lane & 3) * 2;
#pragma unroll
    for (int mf = 0; mf < 4; mf++) {
#pragma unroll
        for (int nf = 0; nf < 4; nf++) {
            const int row = r0 + mf * 16;
            const int col = c0 + nf * 8;
            const float bx = __ldg(bz + col), by = __ldg(bz + col + 1);
            const float v00 = acc[mf][nf][0] + bx, v01 = acc[mf][nf][1] + by;
            const float v10 = acc[mf][nf][2] + bx, v11 = acc[mf][nf][3] + by;
            if (OUTBF == 0) {
                float* Cz = C + (size_t)z * cStride;
                *(float2*)(Cz + (size_t)row * ldc + col)       = make_float2(v00, v01);
                *(float2*)(Cz + (size_t)(row + 8) * ldc + col) = make_float2(v10, v11);
            } else {
                __nv_bfloat16* Chz = Ch + (size_t)z * cStride;
                __nv_bfloat16* Clz = Cl + (size_t)z * cStride;
                const __nv_bfloat16 h00 = __float2bfloat16(v00);
                const __nv_bfloat16 h01 = __float2bfloat16(v01);
                const __nv_bfloat16 h10 = __float2bfloat16(v10);
                const __nv_bfloat16 h11 = __float2bfloat16(v11);
                *(__nv_bfloat162*)(Chz + (size_t)row * ldc + col) = __nv_bfloat162(h00, h01);
                *(__nv_bfloat162*)(Chz + (size_t)(row + 8) * ldc + col) = __nv_bfloat162(h10, h11);
                *(__nv_bfloat162*)(Clz + (size_t)row * ldc + col) =
                    __nv_bfloat162(__float2bfloat16(v00 - __bfloat162float(h00)),
                                   __float2bfloat16(v01 - __bfloat162float(h01)));
                *(__nv_bfloat162*)(Clz + (size_t)(row + 8) * ldc + col) =
                    __nv_bfloat162(__float2bfloat16(v10 - __bfloat162float(h10)),
                                   __float2bfloat16(v11 - __bfloat162float(h11)));
            }
        }
    }
}

// ---------------------------------------------------------------------------
// sin/cos table (double-precision trig once) + table-based rotary+split.
// ---------------------------------------------------------------------------
__global__ __launch_bounds__(64) void rot_table_kernel()
{
    const int p = blockIdx.x, i = threadIdx.x;
    const double freq = exp(9.210340371976184 * ((double)i / 64.0));
    const double ang  = (double)p / freq;
    g_rot[p * 64 + i] = make_float2((float)sin(ang), (float)cos(ang));
}

__global__ __launch_bounds__(128) void rotary_split_kernel(
    const float* __restrict__ X, __nv_bfloat16* __restrict__ H,
    __nv_bfloat16* __restrict__ L, int nheads)
{
    const int p = blockIdx.x;
    const int h = blockIdx.y;
    const int i = threadIdx.x;
    const size_t base = ((size_t)p * nheads + h) * DH;
    const float* row = X + base;

    const int ip = (i < 64) ? i : (i - 64);
    const float2 sc = g_rot[p * 64 + ip];

    const float xi = row[i];
    const float xp = (i < 64) ? row[i + 64] : row[i - 64];
    const float v = (i < 64) ? (xi * sc.y - xp * sc.x) : (xi * sc.y + xp * sc.x);
    const __nv_bfloat16 hv = __float2bfloat16(v);
    H[base + i] = hv;
    L[base + i] = __float2bfloat16(v - __bfloat162float(hv));
}

// ---------------------------------------------------------------------------
// Flash attention on mma.sync bf16 split-3.  BQ=128, BK=64, 256 thr (8 warps).
// smem: Q hi/lo (static) + double-buffered K/V hi/lo.  Row stride 272B.
// ---------------------------------------------------------------------------
#define ARS 272
#define AKT (64 * ARS)                   // 17408: one 64-row operand tile
#define AQT (128 * ARS)                  // 34816: Q tile (128 rows)
#define A_SQH 0
#define A_SQL AQT
#define A_KV0 (2 * AQT)                  // 69632
#define A_STG (4 * AKT)                  // 69632 per stage (Kh,Kl,Vh,Vl)
#define ATTN_SMEM (A_KV0 + 2 * A_STG)    // 208896

__global__ __launch_bounds__(256) void attn_mma_kernel()
{
    extern __shared__ char smem[];
    const uint32_t sb = s2u(smem);
    const int tid  = threadIdx.x;
    const int lane = tid & 31;
    const int wq   = tid >> 5;                 // warp -> q rows [wq*16, +16)
    const int qb   = 15 - blockIdx.x;          // heavy CTAs first
    const int h    = blockIdx.y;
    const int kvh  = h >> 2;
    const int q0   = qb * 128;

    // ---- load Q hi/lo tiles (128 rows) ----
    {
        const int row = tid >> 1;
        const int cb  = (tid & 1) * 8;
        const size_t goff = (size_t)(q0 + row) * DM + h * DH;
#pragma unroll
        for (int j = 0; j < 8; j++) {
            const int c = cb + j;
            cp16(sb + A_SQH + row * ARS + c * 16, g_qAh + goff + c * 8);
            cp16(sb + A_SQL + row * ARS + c * 16, g_qAl + goff + c * 8);
        }
        cp_commit();
    }

    auto load_kv = [&](int kb, int stg) {
        const uint32_t base = sb + A_KV0 + stg * A_STG;
        const int row = tid >> 2;               // 0..63
        const int cb  = (tid & 3) * 4;
        const size_t goff = (size_t)(kb * 64 + row) * (NKV * DH) + kvh * DH;
#pragma unroll
        for (int j = 0; j < 4; j++) {
            const int c = cb + j;
            cp16(base + 0 * AKT + row * ARS + c * 16, g_kAh + goff + c * 8);
            cp16(base + 1 * AKT + row * ARS + c * 16, g_kAl + goff + c * 8);
            cp16(base + 2 * AKT + row * ARS + c * 16, g_vAh + goff + c * 8);
            cp16(base + 3 * AKT + row * ARS + c * 16, g_vAl + goff + c * 8);
        }
        cp_commit();
    };
    load_kv(0, 0);

    float o[16][4];
#pragma unroll
    for (int i = 0; i < 16; i++)
#pragma unroll
        for (int r = 0; r < 4; r++) o[i][r] = 0.f;
    float m0 = -INFINITY, m1 = -INFINITY, l0 = 0.f, l1 = 0.f;

    const uint32_t frag_row = (uint32_t)((lane & 7) + ((lane >> 3) & 1) * 8) * ARS;
    const uint32_t frag_col = ((lane >> 4) & 1) * 16;
    const float SCL = 0.08838834764831845f * 1.4426950408889634f; // scale*log2e

    const int nkb = 2 * qb + 2;
    for (int kb = 0; kb < nkb; kb++) {
        if (kb + 1 < nkb) { load_kv(kb + 1, (kb + 1) & 1); cp_wait<1>(); }
        else              { cp_wait<0>(); }
        __syncthreads();

        const uint32_t skv = sb + A_KV0 + (kb & 1) * A_STG;

        // ---- S = Q K^T (split-3) ----
        float sc[8][4];
#pragma unroll
        for (int i = 0; i < 8; i++)
#pragma unroll
            for (int r = 0; r < 4; r++) sc[i][r] = 0.f;

#pragma unroll
        for (int ks = 0; ks < 8; ks++) {
            const uint32_t qoff = (uint32_t)(wq * 16) * ARS + frag_row + ks * 32 + frag_col;
            uint32_t qh[4], ql[4];
            ldm_x4(qh[0], qh[1], qh[2], qh[3], sb + A_SQH + qoff);
            ldm_x4(ql[0], ql[1], ql[2], ql[3], sb + A_SQL + qoff);
#pragma unroll
            for (int np = 0; np < 4; np++) {
                const uint32_t koff = (uint32_t)(np * 16) * ARS + frag_row + ks * 32 + frag_col;
                uint32_t kh[4], kl[4];
                ldm_x4(kh[0], kh[1], kh[2], kh[3], skv + 0 * AKT + koff);
                ldm_x4(kl[0], kl[1], kl[2], kl[3], skv + 1 * AKT + koff);
                uint32_t bh0[2] = {kh[0], kh[2]}, bh1[2] = {kh[1], kh[3]};
                uint32_t bl0[2] = {kl[0], kl[2]}, bl1[2] = {kl[1], kl[3]};
                mma16816(sc[2 * np],     qh, bh0);
                mma16816(sc[2 * np],     qh, bl0);
                mma16816(sc[2 * np],     ql, bh0);
                mma16816(sc[2 * np + 1], qh, bh1);
                mma16816(sc[2 * np + 1], qh, bl1);
                mma16816(sc[2 * np + 1], ql, bh1);
            }
        }

        // ---- online softmax ----
        const int rg0 = q0 + wq * 16 + (lane >> 2);
        const int rg1 = rg0 + 8;
        const bool diag = (kb >= 2 * qb);
        float mx0 = -INFINITY, mx1 = -INFINITY;
#pragma unroll
        for (int nf = 0; nf < 8; nf++) {
            float t0 = sc[nf][0] * SCL, t1 = sc[nf][1] * SCL;
            float t2 = sc[nf][2] * SCL, t3 = sc[nf][3] * SCL;
            if (diag) {
                const int col = kb * 64 + nf * 8 + (lane & 3) * 2;
                if (col     > rg0) t0 = -INFINITY;
                if (col + 1 > rg0) t1 = -INFINITY;
                if (col     > rg1) t2 = -INFINITY;
                if (col + 1 > rg1) t3 = -INFINITY;
            }
            sc[nf][0] = t0; sc[nf][1] = t1; sc[nf][2] = t2; sc[nf][3] = t3;
            mx0 = fmaxf(mx0, fmaxf(t0, t1));
            mx1 = fmaxf(mx1, fmaxf(t2, t3));
        }
        mx0 = fmaxf(mx0, __shfl_xor_sync(0xffffffffu, mx0, 1));
        mx0 = fmaxf(mx0, __shfl_xor_sync(0xffffffffu, mx0, 2));
        mx1 = fmaxf(mx1, __shfl_xor_sync(0xffffffffu, mx1, 1));
        mx1 = fmaxf(mx1, __shfl_xor_sync(0xffffffffu, mx1, 2));
        const float mn0 = fmaxf(m0, mx0), mn1 = fmaxf(m1, mx1);
        const float corr0 = exp2f(m0 - mn0), corr1 = exp2f(m1 - mn1);
        m0 = mn0; m1 = mn1;

        float rs0 = 0.f, rs1 = 0.f;
#pragma unroll
        for (int nf = 0; nf < 8; nf++) {
            float p0 = exp2f(sc[nf][0] - mn0);
            float p1 = exp2f(sc[nf][1] - mn0);
            float p2 = exp2f(sc[nf][2] - mn1);
            float p3 = exp2f(sc[nf][3] - mn1);
            sc[nf][0] = p0; sc[nf][1] = p1; sc[nf][2] = p2; sc[nf][3] = p3;
            rs0 += p0 + p1; rs1 += p2 + p3;
        }
        rs0 += __shfl_xor_sync(0xffffffffu, rs0, 1);
        rs0 += __shfl_xor_sync(0xffffffffu, rs0, 2);
        rs1 += __shfl_xor_sync(0xffffffffu, rs1, 1);
        rs1 += __shfl_xor_sync(0xffffffffu, rs1, 2);
        l0 = l0 * corr0 + rs0;
        l1 = l1 * corr1 + rs1;
#pragma unroll
        for (int i = 0; i < 16; i++) {
            o[i][0] *= corr0; o[i][1] *= corr0;
            o[i][2] *= corr1; o[i][3] *= corr1;
        }

        // ---- pack P into A fragments (hi + residual lo) ----
        uint32_t pAh[4][4], pAl[4][4];
#pragma unroll
        for (int kg = 0; kg < 4; kg++) {
            const float c0 = sc[2 * kg][0], c1 = sc[2 * kg][1];
            const float c2 = sc[2 * kg][2], c3 = sc[2 * kg][3];
            const float d0 = sc[2 * kg + 1][0], d1 = sc[2 * kg + 1][1];
            const float d2 = sc[2 * kg + 1][2], d3 = sc[2 * kg + 1][3];
            pAh[kg][0] = packbf(c0, c1);
            pAh[kg][1] = packbf(c2, c3);
            pAh[kg][2] = packbf(d0, d1);
            pAh[kg][3] = packbf(d2, d3);
            pAl[kg][0] = packbf(c0 - __bfloat162float(__float2bfloat16(c0)),
                                c1 - __bfloat162float(__float2bfloat16(c1)));
            pAl[kg][1] = packbf(c2 - __bfloat162float(__float2bfloat16(c2)),
                                c3 - __bfloat162float(__float2bfloat16(c3)));
            pAl[kg][2] = packbf(d0 - __bfloat162float(__float2bfloat16(d0)),
                                d1 - __bfloat162float(__float2bfloat16(d1)));
            pAl[kg][3] = packbf(d2 - __bfloat162float(__float2bfloat16(d2)),
                                d3 - __bfloat162float(__float2bfloat16(d3)));
        }

        // ---- O += P V (split-3), V^T via ldmatrix.trans ----
#pragma unroll
        for (int dg = 0; dg < 8; dg++) {
#pragma unroll
            for (int kg = 0; kg < 4; kg++) {
                const uint32_t voff = (uint32_t)(kg * 16) * ARS + frag_row + dg * 32 + frag_col;
                uint32_t vh[4], vl[4];
                ldm_x4_t(vh[0], vh[1], vh[2], vh[3], skv + 2 * AKT + voff);
                ldm_x4_t(vl[0], vl[1], vl[2], vl[3], skv + 3 * AKT + voff);
                uint32_t bh0[2] = {vh[0], vh[1]}, bh1[2] = {vh[2], vh[3]};
                uint32_t bl0[2] = {vl[0], vl[1]}, bl1[2] = {vl[2], vl[3]};
                mma16816(o[2 * dg],     pAh[kg], bh0);
                mma16816(o[2 * dg],     pAh[kg], bl0);
                mma16816(o[2 * dg],     pAl[kg], bh0);
                mma16816(o[2 * dg + 1], pAh[kg], bh1);
                mma16816(o[2 * dg + 1], pAh[kg], bl1);
                mma16816(o[2 * dg + 1], pAl[kg], bh1);
            }
        }
        __syncthreads();
    }

    // ---- epilogue: normalize, split to bf16 hi/lo, store ----
    const float inv0 = 1.f / l0, inv1 = 1.f / l1;
    const int rg0 = q0 + wq * 16 + (lane >> 2);
#pragma unroll
    for (int nf = 0; nf < 16; nf++) {
        const int col = h * DH + nf * 8 + (lane & 3) * 2;
        const float a0 = o[nf][0] * inv0, a1 = o[nf][1] * inv0;
        const float a2 = o[nf][2] * inv1, a3 = o[nf][3] * inv1;
        const __nv_bfloat16 h0 = __float2bfloat16(a0), h1 = __float2bfloat16(a1);
        const __nv_bfloat16 h2 = __float2bfloat16(a2), h3 = __float2bfloat16(a3);
        const size_t b0 = (size_t)rg0 * DM + col;
        const size_t b1 = (size_t)(rg0 + 8) * DM + col;
        *(__nv_bfloat162*)(g_zh + b0) = __nv_bfloat162(h0, h1);
        *(__nv_bfloat162*)(g_zh + b1) = __nv_bfloat162(h2, h3);
        *(__nv_bfloat162*)(g_zl + b0) =
            __nv_bfloat162(__float2bfloat16(a0 - __bfloat162float(h0)),
                           __float2bfloat16(a1 - __bfloat162float(h1)));
        *(__nv_bfloat162*)(g_zl + b1) =
            __nv_bfloat162(__float2bfloat16(a2 - __bfloat162float(h2)),
                           __float2bfloat16(a3 - __bfloat162float(h3)));
    }
}

// ---------------------------------------------------------------------------
template <typename T>
static T* symAddr(const void* sym)
{
    void* p = nullptr;
    cudaGetSymbolAddress(&p, sym);
    return (T*)p;
}

extern "C" void kernel_launch(void* const* d_in, const int* in_sizes, int n_in,
                              void* d_out, int out_size)
{
    const float* Xq = (const float*)d_in[0];
    const float* Xk = (const float*)d_in[1];
    const float* Xv = (const float*)d_in[2];
    const float* WQ = (const float*)d_in[3];
    const float* bQ = (const float*)d_in[4];
    const float* WK = (const float*)d_in[5];
    const float* bK = (const float*)d_in[6];
    const float* WV = (const float*)d_in[7];
    const float* bV = (const float*)d_in[8];
    const float* WO = (const float*)d_in[9];
    const float* bO = (const float*)d_in[10];
    float* out = (float*)d_out;

    float* Qb = symAddr<float>(g_Q);
    float* Kb = symAddr<float>(g_K);
    __nv_bfloat16* xqh = symAddr<__nv_bfloat16>(g_xqh);
    __nv_bfloat16* xql = symAddr<__nv_bfloat16>(g_xql);
    __nv_bfloat16* xkh = symAddr<__nv_bfloat16>(g_xkh);
    __nv_bfloat16* xkl = symAddr<__nv_bfloat16>(g_xkl);
    __nv_bfloat16* xvh = symAddr<__nv_bfloat16>(g_xvh);
    __nv_bfloat16* xvl = symAddr<__nv_bfloat16>(g_xvl);
    __nv_bfloat16* zh  = symAddr<__nv_bfloat16>(g_zh);
    __nv_bfloat16* zl  = symAddr<__nv_bfloat16>(g_zl);
    __nv_bfloat16* wqh = symAddr<__nv_bfloat16>(g_wqh);
    __nv_bfloat16* wql = symAddr<__nv_bfloat16>(g_wql);
    __nv_bfloat16* wkh = symAddr<__nv_bfloat16>(g_wkh);
    __nv_bfloat16* wkl = symAddr<__nv_bfloat16>(g_wkl);
    __nv_bfloat16* wvh = symAddr<__nv_bfloat16>(g_wvh);
    __nv_bfloat16* wvl = symAddr<__nv_bfloat16>(g_wvl);
    __nv_bfloat16* woh = symAddr<__nv_bfloat16>(g_woh);
    __nv_bfloat16* wol = symAddr<__nv_bfloat16>(g_wol);
    __nv_bfloat16* qAh = symAddr<__nv_bfloat16>(g_qAh);
    __nv_bfloat16* qAl = symAddr<__nv_bfloat16>(g_qAl);
    __nv_bfloat16* kAh = symAddr<__nv_bfloat16>(g_kAh);
    __nv_bfloat16* kAl = symAddr<__nv_bfloat16>(g_kAl);
    __nv_bfloat16* vAh = symAddr<__nv_bfloat16>(g_vAh);
    __nv_bfloat16* vAl = symAddr<__nv_bfloat16>(g_vAl);

    cudaFuncSetAttribute(gemm_bf16_kernel<0>,
                         cudaFuncAttributeMaxDynamicSharedMemorySize, GEMM_SMEM);
    cudaFuncSetAttribute(gemm_bf16_kernel<1>,
                         cudaFuncAttributeMaxDynamicSharedMemorySize, GEMM_SMEM);
    cudaFuncSetAttribute(attn_mma_kernel,
                         cudaFuncAttributeMaxDynamicSharedMemorySize, ATTN_SMEM);

    const int nX = SLEN * DM;
    rot_table_kernel<<<SLEN, 64>>>();
    split_kernel<<<nX / 1024, 256>>>(Xq, xqh, xql, nX);
    split_kernel<<<nX / 1024, 256>>>(Xk, xkh, xkl, nX);
    split_kernel<<<nX / 1024, 256>>>(Xv, xvh, xvl, nX);
    transpose_split_kernel<<<dim3(DH / 32, DM / 32, NH),  256>>>(WQ, wqh, wql, DM, DH);
    transpose_split_kernel<<<dim3(DH / 32, DM / 32, NKV), 256>>>(WK, wkh, wkl, DM, DH);
    transpose_split_kernel<<<dim3(DH / 32, DM / 32, NKV), 256>>>(WV, wvh, wvl, DM, DH);
    transpose_split_kernel<<<dim3(DM / 32, DM / 32, 1),   256>>>(WO, woh, wol, DM, DM);

    gemm_bf16_kernel<0><<<dim3(16, 1, NH), 256, GEMM_SMEM>>>(
        xqh, xql, wqh, wql, (long)DH * DM, Qb, nullptr, nullptr, DM, DH, bQ, DH, DM);
    gemm_bf16_kernel<0><<<dim3(16, 1, NKV), 256, GEMM_SMEM>>>(
        xkh, xkl, wkh, wkl, (long)DH * DM, Kb, nullptr, nullptr, NKV * DH, DH, bK, DH, DM);
    gemm_bf16_kernel<1><<<dim3(16, 1, NKV), 256, GEMM_SMEM>>>(
        xvh, xvl, wvh, wvl, (long)DH * DM, nullptr, vAh, vAl, NKV * DH, DH, bV, DH, DM);

    rotary_split_kernel<<<dim3(SLEN, NH),  128>>>(Qb, qAh, qAl, NH);
    rotary_split_kernel<<<dim3(SLEN, NKV), 128>>>(Kb, kAh, kAl, NKV);

    attn_mma_kernel<<<dim3(16, NH), 256, ATTN_SMEM>>>();

    gemm_bf16_kernel<0><<<dim3(16, 16, 1), 256, GEMM_SMEM>>>(
        zh, zl, woh, wol, 0, out, nullptr, nullptr, DM, 0, bO, 0, DM);
}